// round 6
// baseline (speedup 1.0000x reference)
#include <cuda_runtime.h>
#include <cuda_fp16.h>
#include <math.h>
#include <stdint.h>

#define DEPTH   12
#define BATCH   16
#define NTOK    256
#define TOKENS  (BATCH*NTOK)     /* 4096 */
#define DIM     768
#define HEADS   12
#define HD      64
#define HIDDEN  2048
#define EPSF    1e-5f
#define QS      2304             /* packed qkv row stride */
#define GUS     4096             /* packed g|u row stride */

/* ------------------------------------------------------------------ */
/* Scratch buffers                                                     */
/* ------------------------------------------------------------------ */
__device__ float  g_qkv[TOKENS*QS];
__device__ float  g_gu[TOKENS*GUS];
__device__ __half g_yh_hi[TOKENS*DIM];
__device__ __half g_yh_lo[TOKENS*DIM];
__device__ __half g_oh_hi[TOKENS*DIM];
__device__ __half g_oh_lo[TOKENS*DIM];
__device__ __half g_mh_hi[TOKENS*HIDDEN];
__device__ __half g_mh_lo[TOKENS*HIDDEN];

/* packed split weights */
__device__ __half g_wqkv_hi[DEPTH*QS*DIM];
__device__ __half g_wqkv_lo[DEPTH*QS*DIM];
__device__ __half g_wo_hi[DEPTH*DIM*DIM];
__device__ __half g_wo_lo[DEPTH*DIM*DIM];
__device__ __half g_w1_hi[DEPTH*GUS*DIM];
__device__ __half g_w1_lo[DEPTH*GUS*DIM];
__device__ __half g_w2_hi[DEPTH*DIM*HIDDEN];
__device__ __half g_w2_lo[DEPTH*DIM*HIDDEN];
__device__ float  g_bqkv[DEPTH*QS];
__device__ float  g_b1[DEPTH*GUS];

/* ------------------------------------------------------------------ */
/* PTX helpers (baseline sm_80+ only)                                  */
/* ------------------------------------------------------------------ */
__device__ __forceinline__ uint32_t smem_u32(const void* p) {
    uint32_t a;
    asm("{ .reg .u64 t; cvta.to.shared.u64 t, %1; cvt.u32.u64 %0, t; }"
        : "=r"(a) : "l"(p));
    return a;
}
__device__ __forceinline__ void cp16(uint32_t dst, const void* src) {
    asm volatile("cp.async.cg.shared.global [%0], [%1], 16;"
                 :: "r"(dst), "l"(src) : "memory");
}
__device__ __forceinline__ void cp_commit() {
    asm volatile("cp.async.commit_group;" ::: "memory");
}
template<int NWAIT>
__device__ __forceinline__ void cp_wait() {
    asm volatile("cp.async.wait_group %0;" :: "n"(NWAIT) : "memory");
}
__device__ __forceinline__ void ldmx4(uint32_t& r0, uint32_t& r1,
                                      uint32_t& r2, uint32_t& r3, uint32_t a) {
    asm volatile("ldmatrix.sync.aligned.m8n8.x4.shared.b16 {%0,%1,%2,%3}, [%4];"
                 : "=r"(r0), "=r"(r1), "=r"(r2), "=r"(r3) : "r"(a));
}
__device__ __forceinline__ void mma16816(float* c, const uint32_t* a,
                                         uint32_t b0, uint32_t b1) {
    asm("mma.sync.aligned.m16n8k16.row.col.f32.f16.f16.f32 "
        "{%0,%1,%2,%3}, {%4,%5,%6,%7}, {%8,%9}, {%0,%1,%2,%3};"
        : "+f"(c[0]), "+f"(c[1]), "+f"(c[2]), "+f"(c[3])
        : "r"(a[0]), "r"(a[1]), "r"(a[2]), "r"(a[3]), "r"(b0), "r"(b1));
}

/* ------------------------------------------------------------------ */
/* Split-fp16 HMMA GEMM (NT): C = Ahi*Bhi + Ahi*Blo + Alo*Bhi          */
/* (+bias)(+res)(+fused rope). BM=128, BK=64, STAGES-deep cp.async.    */
/* ------------------------------------------------------------------ */
template<int BN, int STAGES, bool ROPE>
__global__ void __launch_bounds__(2*BN, 1) gemm_mma(
    const __half* __restrict__ Ahi, const __half* __restrict__ Alo,
    const __half* __restrict__ Bhi, const __half* __restrict__ Blo,
    const float* __restrict__ bias, const float* __restrict__ res,
    float* __restrict__ C, const float* __restrict__ remb,
    int M, int N, int K) {
    constexpr int T  = 2*BN;
    constexpr int WN = BN/32;
    constexpr int PA = 16384;         /* A plane bytes */
    constexpr int PB = BN*128;        /* B plane bytes */
    constexpr int BUFSZ = 2*PA + 2*PB;
    constexpr int CA = 1024/T;
    constexpr int CB = 4;
    extern __shared__ __align__(128) char smem[];
    uint32_t sb = smem_u32(smem);
    int tid = threadIdx.x, wid = tid >> 5, lane = tid & 31;
    int wm = wid / WN, wn = wid % WN;
    int bm = blockIdx.y * 128, bn = blockIdx.x * BN;

    int l15 = lane & 15, kg = lane >> 4;
    uint32_t arow = (uint32_t)(wm * 64 + l15);
    uint32_t brow = (uint32_t)(wn * 32 + l15);
    int aswz = (int)(arow & 7), bswz = (int)(brow & 7);

    float acc[4][4][4];
    #pragma unroll
    for (int i = 0; i < 4; i++)
        #pragma unroll
        for (int j = 0; j < 4; j++)
            #pragma unroll
            for (int e = 0; e < 4; e++) acc[i][j][e] = 0.f;

    int nch = K >> 6;

    auto load_chunk = [&](uint32_t dst, int ko) {
        #pragma unroll
        for (int j = 0; j < CA; j++) {
            int id = tid + j * T;
            int row = id >> 3, g = id & 7;
            uint32_t off = (uint32_t)row * 128u + (uint32_t)((g ^ (row & 7)) * 16);
            size_t so = (size_t)(bm + row) * K + ko + g * 8;
            cp16(dst + off,      Ahi + so);
            cp16(dst + PA + off, Alo + so);
        }
        #pragma unroll
        for (int j = 0; j < CB; j++) {
            int id = tid + j * T;
            int row = id >> 3, g = id & 7;
            uint32_t off = (uint32_t)row * 128u + (uint32_t)((g ^ (row & 7)) * 16);
            size_t so = (size_t)(bn + row) * K + ko + g * 8;
            cp16(dst + 2*PA + off,      Bhi + so);
            cp16(dst + 2*PA + PB + off, Blo + so);
        }
    };

    #pragma unroll
    for (int s = 0; s < STAGES - 1; s++) {
        load_chunk(sb + (uint32_t)(s * BUFSZ), s * 64);
        cp_commit();
    }

    int cur = 0, nxt = STAGES - 1;
    for (int c = 0; c < nch; c++) {
        if (c + STAGES - 1 < nch) {
            load_chunk(sb + (uint32_t)(nxt * BUFSZ), (c + STAGES - 1) * 64);
            cp_commit();
            nxt = (nxt + 1 == STAGES) ? 0 : nxt + 1;
            cp_wait<STAGES - 1>();
        } else {
            if (c + 1 < nch) cp_wait<1>();
            else             cp_wait<0>();
        }
        __syncthreads();

        uint32_t ba = sb + (uint32_t)(cur * BUFSZ);
        cur = (cur + 1 == STAGES) ? 0 : cur + 1;
        uint32_t a_hi = ba              + arow * 128u;
        uint32_t a_lo = ba + PA         + arow * 128u;
        uint32_t b_hi = ba + 2*PA       + brow * 128u;
        uint32_t b_lo = ba + 2*PA + PB  + brow * 128u;

        #pragma unroll
        for (int ks = 0; ks < 4; ks++) {
            int g = ks * 2 + kg;
            uint32_t goff = (uint32_t)((g ^ aswz) * 16);
            uint32_t gofb = (uint32_t)((g ^ bswz) * 16);
            uint32_t afh[4][4], afl[4][4], bfh[2][4], bfl[2][4];
            #pragma unroll
            for (int mf = 0; mf < 4; mf++) {
                ldmx4(afh[mf][0], afh[mf][1], afh[mf][2], afh[mf][3],
                      a_hi + (uint32_t)(mf * 2048) + goff);
                ldmx4(afl[mf][0], afl[mf][1], afl[mf][2], afl[mf][3],
                      a_lo + (uint32_t)(mf * 2048) + goff);
            }
            #pragma unroll
            for (int nf2 = 0; nf2 < 2; nf2++) {
                ldmx4(bfh[nf2][0], bfh[nf2][1], bfh[nf2][2], bfh[nf2][3],
                      b_hi + (uint32_t)(nf2 * 2048) + gofb);
                ldmx4(bfl[nf2][0], bfl[nf2][1], bfl[nf2][2], bfl[nf2][3],
                      b_lo + (uint32_t)(nf2 * 2048) + gofb);
            }
            #pragma unroll
            for (int mf = 0; mf < 4; mf++)
                #pragma unroll
                for (int nf = 0; nf < 4; nf++)
                    mma16816(acc[mf][nf], afh[mf],
                             bfh[nf >> 1][nf & 1], bfh[nf >> 1][(nf & 1) + 2]);
            #pragma unroll
            for (int mf = 0; mf < 4; mf++)
                #pragma unroll
                for (int nf = 0; nf < 4; nf++)
                    mma16816(acc[mf][nf], afh[mf],
                             bfl[nf >> 1][nf & 1], bfl[nf >> 1][(nf & 1) + 2]);
            #pragma unroll
            for (int mf = 0; mf < 4; mf++)
                #pragma unroll
                for (int nf = 0; nf < 4; nf++)
                    mma16816(acc[mf][nf], afl[mf],
                             bfh[nf >> 1][nf & 1], bfh[nf >> 1][(nf & 1) + 2]);
        }
        __syncthreads();
    }

    /* ---- epilogue (optionally fused RoPE on q|k columns) ---- */
    int r0 = lane >> 2, cb = (lane & 3) * 2;
    #pragma unroll
    for (int mf = 0; mf < 4; mf++) {
        #pragma unroll
        for (int nf = 0; nf < 4; nf++) {
            int n0 = bn + wn * 32 + nf * 8 + cb;
            float bz0 = bias ? bias[n0]     : 0.f;
            float bz1 = bias ? bias[n0 + 1] : 0.f;
            #pragma unroll
            for (int half = 0; half < 2; half++) {
                int m0 = bm + wm * 64 + mf * 16 + r0 + half * 8;
                float v0 = acc[mf][nf][half * 2]     + bz0;
                float v1 = acc[mf][nf][half * 2 + 1] + bz1;
                if (ROPE) {
                    if (n0 < 2*DIM) {
                        int pos = m0 & (NTOK - 1);
                        int d   = n0 & (HD - 1);
                        const float* e = remb + pos * (2*HD);
                        float2 sn = *(const float2*)(e + d);
                        float2 cs = *(const float2*)(e + HD + d);
                        float t0 = v0 * cs.x - v1 * sn.x;
                        float t1 = v1 * cs.y + v0 * sn.y;
                        v0 = t0; v1 = t1;
                    }
                }
                size_t idx = (size_t)m0 * N + n0;
                if (res) { v0 += res[idx]; v1 += res[idx + 1]; }
                *(float2*)(C + idx) = make_float2(v0, v1);
            }
        }
    }
}

/* ------------------------------------------------------------------ */
/* Single fused fp32 -> (hi, lo) split+pack for ALL weights            */
/* ------------------------------------------------------------------ */
struct CvtArgs {
    const float* src[7];
    __half* hi[7];
    __half* lo[7];
    int lr[7];      /* per-layer src elems  */
    int ltot[7];    /* per-layer dst stride */
    int off[7];     /* dst row offset elems */
    int cum[8];     /* cumulative vec4 counts */
};
__device__ __forceinline__ void split2(float a, float b, __half2& h, __half2& l) {
    __half ha = __float2half_rn(a), hb = __float2half_rn(b);
    __half la = __float2half_rn(a - __half2float(ha));
    __half lb = __float2half_rn(b - __half2float(hb));
    h = __halves2half2(ha, hb);
    l = __halves2half2(la, lb);
}
__global__ void cvt_all(CvtArgs a, int total4) {
    int i4 = blockIdx.x * blockDim.x + threadIdx.x;
    if (i4 >= total4) return;
    int s = 0;
    #pragma unroll
    for (int j = 1; j < 7; j++) s += (i4 >= a.cum[j]);
    int i = (i4 - a.cum[s]) * 4;
    int l = i / a.lr[s];
    int rem = i - l * a.lr[s];
    size_t d = (size_t)l * a.ltot[s] + a.off[s] + rem;
    float4 v = *(const float4*)(a.src[s] + i);
    __half2 h0, l0, h1, l1;
    split2(v.x, v.y, h0, l0);
    split2(v.z, v.w, h1, l1);
    ((__half2*)(a.hi[s] + d))[0] = h0; ((__half2*)(a.hi[s] + d))[1] = h1;
    ((__half2*)(a.lo[s] + d))[0] = l0; ((__half2*)(a.lo[s] + d))[1] = l1;
}

__global__ void pack_bias_qkv(const float* __restrict__ bq,
                              const float* __restrict__ bv,
                              float* __restrict__ dst) {
    int i = blockIdx.x * blockDim.x + threadIdx.x;
    if (i >= DEPTH*QS) return;
    int l = i / QS, c = i % QS;
    dst[i] = c < DIM ? bq[l*DIM + c]
           : (c < 2*DIM ? 0.f : bv[l*DIM + c - 2*DIM]);
}
__global__ void pack_bias_mlp(const float* __restrict__ bg,
                              const float* __restrict__ bx,
                              float* __restrict__ dst) {
    int i = blockIdx.x * blockDim.x + threadIdx.x;
    if (i >= DEPTH*GUS) return;
    int l = i / GUS, c = i % GUS;
    dst[i] = c < HIDDEN ? bg[l*HIDDEN + c] : bx[l*HIDDEN + c - HIDDEN];
}

/* ------------------------------------------------------------------ */
/* h = x + pos                                                         */
/* ------------------------------------------------------------------ */
__global__ void add_pos_kernel(const float* __restrict__ x,
                               const float* __restrict__ pos,
                               float* __restrict__ h) {
    int idx = blockIdx.x * blockDim.x + threadIdx.x;
    if (idx < TOKENS*DIM) h[idx] = x[idx] + pos[idx % (NTOK*DIM)];
}

/* ------------------------------------------------------------------ */
/* Block reduction                                                     */
/* ------------------------------------------------------------------ */
__device__ __forceinline__ float2 block_reduce_2(float s, float s2) {
    __shared__ float red[16];
    #pragma unroll
    for (int o = 16; o > 0; o >>= 1) {
        s  += __shfl_down_sync(0xffffffffu, s,  o);
        s2 += __shfl_down_sync(0xffffffffu, s2, o);
    }
    int w = threadIdx.x >> 5, l = threadIdx.x & 31;
    if (l == 0) { red[w] = s; red[8 + w] = s2; }
    __syncthreads();
    if (threadIdx.x < 32) {
        s  = (l < 8) ? red[l]     : 0.f;
        s2 = (l < 8) ? red[8 + l] : 0.f;
        #pragma unroll
        for (int o = 4; o > 0; o >>= 1) {
            s  += __shfl_down_sync(0xffffffffu, s,  o);
            s2 += __shfl_down_sync(0xffffffffu, s2, o);
        }
        if (l == 0) { red[0] = s; red[1] = s2; }
    }
    __syncthreads();
    return make_float2(red[0], red[1]);
}

/* ------------------------------------------------------------------ */
/* LayerNorm (fp32 in, split fp16 out)                                 */
/* ------------------------------------------------------------------ */
__global__ void __launch_bounds__(256) ln_kernel(
    const float* __restrict__ x, const float* __restrict__ w,
    const float* __restrict__ b, __half* __restrict__ ohi,
    __half* __restrict__ olo, int C) {
    int t = blockIdx.x;
    const float* xr = x + (size_t)t * C;
    float s = 0.f, s2 = 0.f;
    for (int c = threadIdx.x; c < C; c += 256) {
        float v = xr[c];
        s += v; s2 += v * v;
    }
    float2 r = block_reduce_2(s, s2);
    float mean = r.x / C;
    float var  = r.y / C - mean * mean;
    float inv  = rsqrtf(var + EPSF);
    for (int c = threadIdx.x; c < C; c += 256) {
        float v = (xr[c] - mean) * inv * w[c] + b[c];
        __half h = __float2half_rn(v);
        ohi[(size_t)t * C + c] = h;
        olo[(size_t)t * C + c] = __float2half_rn(v - __half2float(h));
    }
}

/* ------------------------------------------------------------------ */
/* silu(g)*u then LN over HIDDEN; g|u packed row stride GUS            */
/* ------------------------------------------------------------------ */
__global__ void __launch_bounds__(256) mlp_act_ln_kernel(
    const float* __restrict__ gu,
    const float* __restrict__ w, const float* __restrict__ b,
    __half* __restrict__ ohi, __half* __restrict__ olo) {
    int t = blockIdx.x;
    __shared__ float buf[HIDDEN];
    const float* gr = gu + (size_t)t * GUS;
    const float* ur = gr + HIDDEN;
    float s = 0.f, s2 = 0.f;
    for (int c = threadIdx.x; c < HIDDEN; c += 256) {
        float gv = gr[c];
        float a  = gv / (1.f + __expf(-gv)) * ur[c];
        buf[c] = a;
        s += a; s2 += a * a;
    }
    __syncthreads();
    float2 r = block_reduce_2(s, s2);
    float mean = r.x / HIDDEN;
    float var  = r.y / HIDDEN - mean * mean;
    float inv  = rsqrtf(var + EPSF);
    for (int c = threadIdx.x; c < HIDDEN; c += 256) {
        float v = (buf[c] - mean) * inv * w[c] + b[c];
        __half h = __float2half_rn(v);
        ohi[(size_t)t * HIDDEN + c] = h;
        olo[(size_t)t * HIDDEN + c] = __float2half_rn(v - __half2float(h));
    }
}

/* ------------------------------------------------------------------ */
/* Attention: 2 lanes per query row (32-dim slices), KV tiled x128.    */
/* ------------------------------------------------------------------ */
#define KVT 128
__global__ void __launch_bounds__(256) attn_kernel(
    const float* __restrict__ qkv, __half* __restrict__ ohi,
    __half* __restrict__ olo) {
    extern __shared__ float sm[];
    float* Ks = sm;
    float* Vs = sm + KVT * HD;
    int blk = blockIdx.x;
    int half_blk = blk & 1;
    int bh = blk >> 1;
    int b  = bh / HEADS, h = bh % HEADS;
    size_t base_q = (size_t)(b * NTOK) * QS + h * HD;
    int tid = threadIdx.x, lane = tid & 31, wid = tid >> 5;
    int row_local = wid * 16 + (lane & 15);
    int part = lane >> 4;
    int i = half_blk * 128 + row_local;

    const float scale = 0.125f;
    float qreg[32];
    {
        const float* qp = qkv + base_q + (size_t)i * QS + part * 32;
        #pragma unroll
        for (int d = 0; d < 32; d++) qreg[d] = qp[d] * scale;
    }

    float mrun = -1e30f, lrun = 0.f;
    float accv[32];
    #pragma unroll
    for (int d = 0; d < 32; d++) accv[d] = 0.f;

    for (int tkv = 0; tkv < NTOK / KVT; tkv++) {
        for (int idx = tid; idx < KVT * HD; idx += 256) {
            int row = idx >> 6, col = idx & 63;
            size_t src = base_q + (size_t)(tkv * KVT + row) * QS + col;
            Ks[idx] = qkv[src + DIM];
            Vs[idx] = qkv[src + 2*DIM];
        }
        __syncthreads();

        for (int j = 0; j < KVT; j++) {
            const float* kr = Ks + j * HD + part * 32;
            float s = 0.f;
            #pragma unroll
            for (int d = 0; d < 32; d++) s += qreg[d] * kr[d];
            s += __shfl_xor_sync(0xffffffffu, s, 16);
            float mnew = fmaxf(mrun, s);
            float cc = __expf(mrun - mnew);
            float p  = __expf(s - mnew);
            lrun = lrun * cc + p;
            const float* vr = Vs + j * HD + part * 32;
            #pragma unroll
            for (int d = 0; d < 32; d++) accv[d] = accv[d] * cc + p * vr[d];
            mrun = mnew;
        }
        __syncthreads();
    }

    float inv = 1.f / lrun;
    size_t ob = (size_t)(b * NTOK + i) * DIM + h * HD + part * 32;
    #pragma unroll
    for (int d = 0; d < 32; d++) {
        float v0 = accv[d] * inv;
        __half hh = __float2half_rn(v0);
        ohi[ob + d] = hh;
        olo[ob + d] = __float2half_rn(v0 - __half2float(hh));
    }
}

/* ------------------------------------------------------------------ */
/* Launch                                                              */
/* ------------------------------------------------------------------ */
extern "C" void kernel_launch(void* const* d_in, const int* in_sizes, int n_in,
                              void* d_out, int out_size) {
    const float* x      = (const float*)d_in[0];
    const float* pos    = (const float*)d_in[1];
    const float* rope   = (const float*)d_in[2];
    const float* ln1_w  = (const float*)d_in[3];
    const float* ln1_b  = (const float*)d_in[4];
    const float* wq     = (const float*)d_in[5];
    const float* bq     = (const float*)d_in[6];
    const float* wk     = (const float*)d_in[7];
    const float* wv     = (const float*)d_in[8];
    const float* bv     = (const float*)d_in[9];
    const float* wo     = (const float*)d_in[10];
    const float* bo     = (const float*)d_in[11];
    const float* ln2_w  = (const float*)d_in[12];
    const float* ln2_b  = (const float*)d_in[13];
    const float* w1g    = (const float*)d_in[14];
    const float* b1g    = (const float*)d_in[15];
    const float* w1x    = (const float*)d_in[16];
    const float* b1x    = (const float*)d_in[17];
    const float* lnm_w  = (const float*)d_in[18];
    const float* lnm_b  = (const float*)d_in[19];
    const float* w2     = (const float*)d_in[20];
    const float* b2     = (const float*)d_in[21];
    float* h = (float*)d_out;

    float *qkv, *gu, *bqkv, *b1;
    __half *yhh, *yhl, *ohh, *ohl, *mhh, *mhl;
    __half *wqkvh, *wqkvl, *woh, *wol, *w1h, *w1l, *w2h, *w2l;
    cudaGetSymbolAddress((void**)&qkv,   g_qkv);
    cudaGetSymbolAddress((void**)&gu,    g_gu);
    cudaGetSymbolAddress((void**)&bqkv,  g_bqkv);
    cudaGetSymbolAddress((void**)&b1,    g_b1);
    cudaGetSymbolAddress((void**)&yhh,   g_yh_hi);
    cudaGetSymbolAddress((void**)&yhl,   g_yh_lo);
    cudaGetSymbolAddress((void**)&ohh,   g_oh_hi);
    cudaGetSymbolAddress((void**)&ohl,   g_oh_lo);
    cudaGetSymbolAddress((void**)&mhh,   g_mh_hi);
    cudaGetSymbolAddress((void**)&mhl,   g_mh_lo);
    cudaGetSymbolAddress((void**)&wqkvh, g_wqkv_hi);
    cudaGetSymbolAddress((void**)&wqkvl, g_wqkv_lo);
    cudaGetSymbolAddress((void**)&woh,   g_wo_hi);
    cudaGetSymbolAddress((void**)&wol,   g_wo_lo);
    cudaGetSymbolAddress((void**)&w1h,   g_w1_hi);
    cudaGetSymbolAddress((void**)&w1l,   g_w1_lo);
    cudaGetSymbolAddress((void**)&w2h,   g_w2_hi);
    cudaGetSymbolAddress((void**)&w2l,   g_w2_lo);

    const int SM128 = 3*(2*16384 + 2*128*128);   /* 196608, 3-stage */
    const int SM256 = 2*(2*16384 + 2*256*128);   /* 196608, 2-stage */
    cudaFuncSetAttribute((const void*)gemm_mma<128,3,false>,
                         cudaFuncAttributeMaxDynamicSharedMemorySize, SM128);
    cudaFuncSetAttribute((const void*)gemm_mma<256,2,true>,
                         cudaFuncAttributeMaxDynamicSharedMemorySize, SM256);
    cudaFuncSetAttribute((const void*)gemm_mma<256,2,false>,
                         cudaFuncAttributeMaxDynamicSharedMemorySize, SM256);
    cudaFuncSetAttribute((const void*)attn_kernel,
                         cudaFuncAttributeMaxDynamicSharedMemorySize,
                         2 * KVT * HD * (int)sizeof(float));

    /* ---- fused weight split + packing (1 launch) ---- */
    {
        const int nD = DIM*DIM, nH = HIDDEN*DIM;
        CvtArgs a;
        const float* srcs[7] = { wq, wk, wv, wo, w1g, w1x, w2 };
        __half* his[7] = { wqkvh, wqkvh, wqkvh, woh, w1h, w1h, w2h };
        __half* los[7] = { wqkvl, wqkvl, wqkvl, wol, w1l, w1l, w2l };
        int lrs[7]   = { nD, nD, nD, nD, nH, nH, nH };
        int ltots[7] = { QS*DIM, QS*DIM, QS*DIM, nD, GUS*DIM, GUS*DIM, nH };
        int offs[7]  = { 0, nD, 2*nD, 0, 0, nH, 0 };
        int cum = 0;
        for (int s = 0; s < 7; s++) {
            a.src[s] = srcs[s]; a.hi[s] = his[s]; a.lo[s] = los[s];
            a.lr[s] = lrs[s]; a.ltot[s] = ltots[s]; a.off[s] = offs[s];
            a.cum[s] = cum;
            cum += DEPTH * lrs[s] / 4;
        }
        a.cum[7] = cum;
        cvt_all<<<(cum + 255)/256, 256>>>(a, cum);
        pack_bias_qkv<<<(DEPTH*QS + 255)/256, 256>>>(bq, bv, bqkv);
        pack_bias_mlp<<<(DEPTH*GUS + 255)/256, 256>>>(b1g, b1x, b1);
    }

    add_pos_kernel<<<(TOKENS*DIM + 255)/256, 256>>>(x, pos, h);

    dim3 gQKV(QS/256,  TOKENS/128);   /* (9, 32)  */
    dim3 gMLP(GUS/256, TOKENS/128);   /* (16, 32) */
    dim3 gO  (DIM/128, TOKENS/128);   /* (6, 32)  */

    for (int l = 0; l < DEPTH; l++) {
        size_t oqkv = (size_t)l * QS * DIM;
        size_t owo  = (size_t)l * DIM * DIM;
        size_t ow1  = (size_t)l * GUS * DIM;
        size_t ow2  = (size_t)l * DIM * HIDDEN;

        /* ---- attention ---- */
        ln_kernel<<<TOKENS, 256>>>(h, ln1_w + l*DIM, ln1_b + l*DIM, yhh, yhl, DIM);
        gemm_mma<256,2,true><<<gQKV, 512, SM256>>>(
            yhh, yhl, wqkvh + oqkv, wqkvl + oqkv,
            bqkv + l*QS, nullptr, qkv, rope, TOKENS, QS, DIM);
        attn_kernel<<<BATCH*HEADS*2, 256, 2*KVT*HD*sizeof(float)>>>(qkv, ohh, ohl);
        gemm_mma<128,3,false><<<gO, 256, SM128>>>(
            ohh, ohl, woh + owo, wol + owo,
            bo + l*DIM, h, h, nullptr, TOKENS, DIM, DIM);

        /* ---- SwiGLU MLP ---- */
        ln_kernel<<<TOKENS, 256>>>(h, ln2_w + l*DIM, ln2_b + l*DIM, yhh, yhl, DIM);
        gemm_mma<256,2,false><<<gMLP, 512, SM256>>>(
            yhh, yhl, w1h + ow1, w1l + ow1,
            b1 + l*GUS, nullptr, gu, nullptr, TOKENS, GUS, DIM);
        mlp_act_ln_kernel<<<TOKENS, 256>>>(gu, lnm_w + l*HIDDEN, lnm_b + l*HIDDEN, mhh, mhl);
        gemm_mma<128,3,false><<<gO, 256, SM128>>>(
            mhh, mhl, w2h + ow2, w2l + ow2,
            b2 + l*DIM, h, h, nullptr, TOKENS, DIM, HIDDEN);
    }
}

// round 7
// speedup vs baseline: 1.0553x; 1.0553x over previous
#include <cuda_runtime.h>
#include <cuda_fp16.h>
#include <math.h>
#include <stdint.h>

#define DEPTH   12
#define BATCH   16
#define NTOK    256
#define TOKENS  (BATCH*NTOK)     /* 4096 */
#define DIM     768
#define HEADS   12
#define HD      64
#define HIDDEN  2048
#define EPSF    1e-5f
#define QS      2304             /* packed qkv row stride */
#define GUS     4096             /* packed g|u row stride */

/* ------------------------------------------------------------------ */
/* Scratch buffers                                                     */
/* ------------------------------------------------------------------ */
__device__ float  g_qkv[TOKENS*QS];
__device__ float  g_gu[TOKENS*GUS];
__device__ __half g_yh_hi[TOKENS*DIM];
__device__ __half g_yh_lo[TOKENS*DIM];
__device__ __half g_oh_hi[TOKENS*DIM];
__device__ __half g_oh_lo[TOKENS*DIM];
__device__ __half g_mh_hi[TOKENS*HIDDEN];
__device__ __half g_mh_lo[TOKENS*HIDDEN];

/* packed split weights */
__device__ __half g_wqkv_hi[DEPTH*QS*DIM];
__device__ __half g_wqkv_lo[DEPTH*QS*DIM];
__device__ __half g_wo_hi[DEPTH*DIM*DIM];
__device__ __half g_wo_lo[DEPTH*DIM*DIM];
__device__ __half g_w1_hi[DEPTH*GUS*DIM];
__device__ __half g_w1_lo[DEPTH*GUS*DIM];
__device__ __half g_w2_hi[DEPTH*DIM*HIDDEN];
__device__ __half g_w2_lo[DEPTH*DIM*HIDDEN];
__device__ float  g_bqkv[DEPTH*QS];
__device__ float  g_b1[DEPTH*GUS];

/* ------------------------------------------------------------------ */
/* PTX helpers (baseline sm_80+ only)                                  */
/* ------------------------------------------------------------------ */
__device__ __forceinline__ uint32_t smem_u32(const void* p) {
    uint32_t a;
    asm("{ .reg .u64 t; cvta.to.shared.u64 t, %1; cvt.u32.u64 %0, t; }"
        : "=r"(a) : "l"(p));
    return a;
}
__device__ __forceinline__ void cp16(uint32_t dst, const void* src) {
    asm volatile("cp.async.cg.shared.global [%0], [%1], 16;"
                 :: "r"(dst), "l"(src) : "memory");
}
__device__ __forceinline__ void cp_commit() {
    asm volatile("cp.async.commit_group;" ::: "memory");
}
template<int NWAIT>
__device__ __forceinline__ void cp_wait() {
    asm volatile("cp.async.wait_group %0;" :: "n"(NWAIT) : "memory");
}
__device__ __forceinline__ void ldmx4(uint32_t& r0, uint32_t& r1,
                                      uint32_t& r2, uint32_t& r3, uint32_t a) {
    asm volatile("ldmatrix.sync.aligned.m8n8.x4.shared.b16 {%0,%1,%2,%3}, [%4];"
                 : "=r"(r0), "=r"(r1), "=r"(r2), "=r"(r3) : "r"(a));
}
__device__ __forceinline__ void mma16816(float* c, const uint32_t* a,
                                         uint32_t b0, uint32_t b1) {
    asm("mma.sync.aligned.m16n8k16.row.col.f32.f16.f16.f32 "
        "{%0,%1,%2,%3}, {%4,%5,%6,%7}, {%8,%9}, {%0,%1,%2,%3};"
        : "+f"(c[0]), "+f"(c[1]), "+f"(c[2]), "+f"(c[3])
        : "r"(a[0]), "r"(a[1]), "r"(a[2]), "r"(a[3]), "r"(b0), "r"(b1));
}

/* ------------------------------------------------------------------ */
/* Split-fp16 HMMA GEMM (NT): C = Ahi*Bhi + Ahi*Blo + Alo*Bhi          */
/* (+bias)(+res)(+fused rope).                                         */
/* CTA tile 128x256, 8 warps of 64x64 (2x4), BK=64, double-buffered.   */
/* ------------------------------------------------------------------ */
#define PA 16384                       /* A plane bytes (128 x 128B) */
#define PB 32768                       /* B plane bytes (256 x 128B) */
#define BUFSZ (2*PA + 2*PB)            /* 98304 */
#define GEMM_SMEM (2*BUFSZ)            /* 196608 */

template<bool ROPE>
__global__ void __launch_bounds__(256, 1) gemm_mma(
    const __half* __restrict__ Ahi, const __half* __restrict__ Alo,
    const __half* __restrict__ Bhi, const __half* __restrict__ Blo,
    const float* __restrict__ bias, const float* __restrict__ res,
    float* __restrict__ C, const float* __restrict__ remb,
    int M, int N, int K) {
    extern __shared__ __align__(128) char smem[];
    uint32_t sb = smem_u32(smem);
    int tid = threadIdx.x, wid = tid >> 5, lane = tid & 31;
    int wm = wid >> 2, wn = wid & 3;       /* 2 x 4 grid of 64x64 tiles */
    int bm = blockIdx.y * 128, bn = blockIdx.x * 256;

    int l15 = lane & 15, kg = lane >> 4;
    uint32_t arow = (uint32_t)(wm * 64 + l15);
    uint32_t brow = (uint32_t)(wn * 64 + l15);
    int aswz = (int)(arow & 7), bswz = (int)(brow & 7);

    float acc[4][8][4];
    #pragma unroll
    for (int i = 0; i < 4; i++)
        #pragma unroll
        for (int j = 0; j < 8; j++)
            #pragma unroll
            for (int e = 0; e < 4; e++) acc[i][j][e] = 0.f;

    int nch = K >> 6;

    auto load_chunk = [&](uint32_t dst, int ko) {
        #pragma unroll
        for (int j = 0; j < 4; j++) {              /* A: 1024 chunks/plane */
            int id = tid + j * 256;
            int row = id >> 3, g = id & 7;
            uint32_t off = (uint32_t)row * 128u + (uint32_t)((g ^ (row & 7)) * 16);
            size_t so = (size_t)(bm + row) * K + ko + g * 8;
            cp16(dst + off,      Ahi + so);
            cp16(dst + PA + off, Alo + so);
        }
        #pragma unroll
        for (int j = 0; j < 8; j++) {              /* B: 2048 chunks/plane */
            int id = tid + j * 256;
            int row = id >> 3, g = id & 7;
            uint32_t off = (uint32_t)row * 128u + (uint32_t)((g ^ (row & 7)) * 16);
            size_t so = (size_t)(bn + row) * K + ko + g * 8;
            cp16(dst + 2*PA + off,      Bhi + so);
            cp16(dst + 2*PA + PB + off, Blo + so);
        }
    };

    load_chunk(sb, 0);
    cp_commit();

    for (int c = 0; c < nch; c++) {
        if (c + 1 < nch) {
            load_chunk(sb + (uint32_t)(((c + 1) & 1) * BUFSZ), (c + 1) * 64);
            cp_commit();
            cp_wait<1>();
        } else {
            cp_wait<0>();
        }
        __syncthreads();

        uint32_t ba = sb + (uint32_t)((c & 1) * BUFSZ);
        uint32_t a_hi = ba             + arow * 128u;
        uint32_t a_lo = ba + PA        + arow * 128u;
        uint32_t b_hi = ba + 2*PA      + brow * 128u;
        uint32_t b_lo = ba + 2*PA + PB + brow * 128u;

        #pragma unroll
        for (int ks = 0; ks < 4; ks++) {
            int g = ks * 2 + kg;
            uint32_t goff = (uint32_t)((g ^ aswz) * 16);
            uint32_t gofb = (uint32_t)((g ^ bswz) * 16);
            uint32_t afh[4][4], afl[4][4], bfh[4][4], bfl[4][4];
            #pragma unroll
            for (int mf = 0; mf < 4; mf++) {
                ldmx4(afh[mf][0], afh[mf][1], afh[mf][2], afh[mf][3],
                      a_hi + (uint32_t)(mf * 2048) + goff);
                ldmx4(afl[mf][0], afl[mf][1], afl[mf][2], afl[mf][3],
                      a_lo + (uint32_t)(mf * 2048) + goff);
            }
            #pragma unroll
            for (int nf2 = 0; nf2 < 4; nf2++) {
                ldmx4(bfh[nf2][0], bfh[nf2][1], bfh[nf2][2], bfh[nf2][3],
                      b_hi + (uint32_t)(nf2 * 2048) + gofb);
                ldmx4(bfl[nf2][0], bfl[nf2][1], bfl[nf2][2], bfl[nf2][3],
                      b_lo + (uint32_t)(nf2 * 2048) + gofb);
            }
            /* term-outer: 32 independent accumulators between reuse */
            #pragma unroll
            for (int mf = 0; mf < 4; mf++)
                #pragma unroll
                for (int nf = 0; nf < 8; nf++)
                    mma16816(acc[mf][nf], afh[mf],
                             bfh[nf >> 1][nf & 1], bfh[nf >> 1][(nf & 1) + 2]);
            #pragma unroll
            for (int mf = 0; mf < 4; mf++)
                #pragma unroll
                for (int nf = 0; nf < 8; nf++)
                    mma16816(acc[mf][nf], afh[mf],
                             bfl[nf >> 1][nf & 1], bfl[nf >> 1][(nf & 1) + 2]);
            #pragma unroll
            for (int mf = 0; mf < 4; mf++)
                #pragma unroll
                for (int nf = 0; nf < 8; nf++)
                    mma16816(acc[mf][nf], afl[mf],
                             bfh[nf >> 1][nf & 1], bfh[nf >> 1][(nf & 1) + 2]);
        }
        __syncthreads();
    }

    /* ---- epilogue (optionally fused RoPE on q|k columns) ---- */
    int r0 = lane >> 2, cb = (lane & 3) * 2;
    #pragma unroll
    for (int mf = 0; mf < 4; mf++) {
        #pragma unroll
        for (int nf = 0; nf < 8; nf++) {
            int n0 = bn + wn * 64 + nf * 8 + cb;
            float bz0 = bias ? bias[n0]     : 0.f;
            float bz1 = bias ? bias[n0 + 1] : 0.f;
            #pragma unroll
            for (int half = 0; half < 2; half++) {
                int m0 = bm + wm * 64 + mf * 16 + r0 + half * 8;
                float v0 = acc[mf][nf][half * 2]     + bz0;
                float v1 = acc[mf][nf][half * 2 + 1] + bz1;
                if (ROPE) {
                    if (n0 < 2*DIM) {
                        int pos = m0 & (NTOK - 1);
                        int d   = n0 & (HD - 1);
                        const float* e = remb + pos * (2*HD);
                        float2 sn = *(const float2*)(e + d);
                        float2 cs = *(const float2*)(e + HD + d);
                        float t0 = v0 * cs.x - v1 * sn.x;
                        float t1 = v1 * cs.y + v0 * sn.y;
                        v0 = t0; v1 = t1;
                    }
                }
                size_t idx = (size_t)m0 * N + n0;
                if (res) { v0 += res[idx]; v1 += res[idx + 1]; }
                *(float2*)(C + idx) = make_float2(v0, v1);
            }
        }
    }
}

/* ------------------------------------------------------------------ */
/* Single fused fp32 -> (hi, lo) split+pack for ALL weights            */
/* ------------------------------------------------------------------ */
struct CvtArgs {
    const float* src[7];
    __half* hi[7];
    __half* lo[7];
    int lr[7];
    int ltot[7];
    int off[7];
    int cum[8];
};
__device__ __forceinline__ void split2(float a, float b, __half2& h, __half2& l) {
    __half ha = __float2half_rn(a), hb = __float2half_rn(b);
    __half la = __float2half_rn(a - __half2float(ha));
    __half lb = __float2half_rn(b - __half2float(hb));
    h = __halves2half2(ha, hb);
    l = __halves2half2(la, lb);
}
__global__ void cvt_all(CvtArgs a, int total4) {
    int i4 = blockIdx.x * blockDim.x + threadIdx.x;
    if (i4 >= total4) return;
    int s = 0;
    #pragma unroll
    for (int j = 1; j < 7; j++) s += (i4 >= a.cum[j]);
    int i = (i4 - a.cum[s]) * 4;
    int l = i / a.lr[s];
    int rem = i - l * a.lr[s];
    size_t d = (size_t)l * a.ltot[s] + a.off[s] + rem;
    float4 v = *(const float4*)(a.src[s] + i);
    __half2 h0, l0, h1, l1;
    split2(v.x, v.y, h0, l0);
    split2(v.z, v.w, h1, l1);
    ((__half2*)(a.hi[s] + d))[0] = h0; ((__half2*)(a.hi[s] + d))[1] = h1;
    ((__half2*)(a.lo[s] + d))[0] = l0; ((__half2*)(a.lo[s] + d))[1] = l1;
}

__global__ void pack_bias_qkv(const float* __restrict__ bq,
                              const float* __restrict__ bv,
                              float* __restrict__ dst) {
    int i = blockIdx.x * blockDim.x + threadIdx.x;
    if (i >= DEPTH*QS) return;
    int l = i / QS, c = i % QS;
    dst[i] = c < DIM ? bq[l*DIM + c]
           : (c < 2*DIM ? 0.f : bv[l*DIM + c - 2*DIM]);
}
__global__ void pack_bias_mlp(const float* __restrict__ bg,
                              const float* __restrict__ bx,
                              float* __restrict__ dst) {
    int i = blockIdx.x * blockDim.x + threadIdx.x;
    if (i >= DEPTH*GUS) return;
    int l = i / GUS, c = i % GUS;
    dst[i] = c < HIDDEN ? bg[l*HIDDEN + c] : bx[l*HIDDEN + c - HIDDEN];
}

/* ------------------------------------------------------------------ */
/* h = x + pos                                                         */
/* ------------------------------------------------------------------ */
__global__ void add_pos_kernel(const float* __restrict__ x,
                               const float* __restrict__ pos,
                               float* __restrict__ h) {
    int idx = blockIdx.x * blockDim.x + threadIdx.x;
    if (idx < TOKENS*DIM) h[idx] = x[idx] + pos[idx % (NTOK*DIM)];
}

/* ------------------------------------------------------------------ */
/* Block reduction                                                     */
/* ------------------------------------------------------------------ */
__device__ __forceinline__ float2 block_reduce_2(float s, float s2) {
    __shared__ float red[16];
    #pragma unroll
    for (int o = 16; o > 0; o >>= 1) {
        s  += __shfl_down_sync(0xffffffffu, s,  o);
        s2 += __shfl_down_sync(0xffffffffu, s2, o);
    }
    int w = threadIdx.x >> 5, l = threadIdx.x & 31;
    if (l == 0) { red[w] = s; red[8 + w] = s2; }
    __syncthreads();
    if (threadIdx.x < 32) {
        s  = (l < 8) ? red[l]     : 0.f;
        s2 = (l < 8) ? red[8 + l] : 0.f;
        #pragma unroll
        for (int o = 4; o > 0; o >>= 1) {
            s  += __shfl_down_sync(0xffffffffu, s,  o);
            s2 += __shfl_down_sync(0xffffffffu, s2, o);
        }
        if (l == 0) { red[0] = s; red[1] = s2; }
    }
    __syncthreads();
    return make_float2(red[0], red[1]);
}

/* ------------------------------------------------------------------ */
/* LayerNorm (fp32 in, split fp16 out)                                 */
/* ------------------------------------------------------------------ */
__global__ void __launch_bounds__(256) ln_kernel(
    const float* __restrict__ x, const float* __restrict__ w,
    const float* __restrict__ b, __half* __restrict__ ohi,
    __half* __restrict__ olo, int C) {
    int t = blockIdx.x;
    const float* xr = x + (size_t)t * C;
    float s = 0.f, s2 = 0.f;
    for (int c = threadIdx.x; c < C; c += 256) {
        float v = xr[c];
        s += v; s2 += v * v;
    }
    float2 r = block_reduce_2(s, s2);
    float mean = r.x / C;
    float var  = r.y / C - mean * mean;
    float inv  = rsqrtf(var + EPSF);
    for (int c = threadIdx.x; c < C; c += 256) {
        float v = (xr[c] - mean) * inv * w[c] + b[c];
        __half h = __float2half_rn(v);
        ohi[(size_t)t * C + c] = h;
        olo[(size_t)t * C + c] = __float2half_rn(v - __half2float(h));
    }
}

/* ------------------------------------------------------------------ */
/* silu(g)*u then LN over HIDDEN; g|u packed row stride GUS            */
/* ------------------------------------------------------------------ */
__global__ void __launch_bounds__(256) mlp_act_ln_kernel(
    const float* __restrict__ gu,
    const float* __restrict__ w, const float* __restrict__ b,
    __half* __restrict__ ohi, __half* __restrict__ olo) {
    int t = blockIdx.x;
    __shared__ float buf[HIDDEN];
    const float* gr = gu + (size_t)t * GUS;
    const float* ur = gr + HIDDEN;
    float s = 0.f, s2 = 0.f;
    for (int c = threadIdx.x; c < HIDDEN; c += 256) {
        float gv = gr[c];
        float a  = gv / (1.f + __expf(-gv)) * ur[c];
        buf[c] = a;
        s += a; s2 += a * a;
    }
    __syncthreads();
    float2 r = block_reduce_2(s, s2);
    float mean = r.x / HIDDEN;
    float var  = r.y / HIDDEN - mean * mean;
    float inv  = rsqrtf(var + EPSF);
    for (int c = threadIdx.x; c < HIDDEN; c += 256) {
        float v = (buf[c] - mean) * inv * w[c] + b[c];
        __half h = __float2half_rn(v);
        ohi[(size_t)t * HIDDEN + c] = h;
        olo[(size_t)t * HIDDEN + c] = __float2half_rn(v - __half2float(h));
    }
}

/* ------------------------------------------------------------------ */
/* Attention: 2 lanes per query row (32-dim slices), KV tiled x128.    */
/* ------------------------------------------------------------------ */
#define KVT 128
__global__ void __launch_bounds__(256) attn_kernel(
    const float* __restrict__ qkv, __half* __restrict__ ohi,
    __half* __restrict__ olo) {
    extern __shared__ float sm[];
    float* Ks = sm;
    float* Vs = sm + KVT * HD;
    int blk = blockIdx.x;
    int half_blk = blk & 1;
    int bh = blk >> 1;
    int b  = bh / HEADS, h = bh % HEADS;
    size_t base_q = (size_t)(b * NTOK) * QS + h * HD;
    int tid = threadIdx.x, lane = tid & 31, wid = tid >> 5;
    int row_local = wid * 16 + (lane & 15);
    int part = lane >> 4;
    int i = half_blk * 128 + row_local;

    const float scale = 0.125f;
    float qreg[32];
    {
        const float* qp = qkv + base_q + (size_t)i * QS + part * 32;
        #pragma unroll
        for (int d = 0; d < 32; d++) qreg[d] = qp[d] * scale;
    }

    float mrun = -1e30f, lrun = 0.f;
    float accv[32];
    #pragma unroll
    for (int d = 0; d < 32; d++) accv[d] = 0.f;

    for (int tkv = 0; tkv < NTOK / KVT; tkv++) {
        for (int idx = tid; idx < KVT * HD; idx += 256) {
            int row = idx >> 6, col = idx & 63;
            size_t src = base_q + (size_t)(tkv * KVT + row) * QS + col;
            Ks[idx] = qkv[src + DIM];
            Vs[idx] = qkv[src + 2*DIM];
        }
        __syncthreads();

        for (int j = 0; j < KVT; j++) {
            const float* kr = Ks + j * HD + part * 32;
            float s = 0.f;
            #pragma unroll
            for (int d = 0; d < 32; d++) s += qreg[d] * kr[d];
            s += __shfl_xor_sync(0xffffffffu, s, 16);
            float mnew = fmaxf(mrun, s);
            float cc = __expf(mrun - mnew);
            float p  = __expf(s - mnew);
            lrun = lrun * cc + p;
            const float* vr = Vs + j * HD + part * 32;
            #pragma unroll
            for (int d = 0; d < 32; d++) accv[d] = accv[d] * cc + p * vr[d];
            mrun = mnew;
        }
        __syncthreads();
    }

    float inv = 1.f / lrun;
    size_t ob = (size_t)(b * NTOK + i) * DIM + h * HD + part * 32;
    #pragma unroll
    for (int d = 0; d < 32; d++) {
        float v0 = accv[d] * inv;
        __half hh = __float2half_rn(v0);
        ohi[ob + d] = hh;
        olo[ob + d] = __float2half_rn(v0 - __half2float(hh));
    }
}

/* ------------------------------------------------------------------ */
/* Launch                                                              */
/* ------------------------------------------------------------------ */
extern "C" void kernel_launch(void* const* d_in, const int* in_sizes, int n_in,
                              void* d_out, int out_size) {
    const float* x      = (const float*)d_in[0];
    const float* pos    = (const float*)d_in[1];
    const float* rope   = (const float*)d_in[2];
    const float* ln1_w  = (const float*)d_in[3];
    const float* ln1_b  = (const float*)d_in[4];
    const float* wq     = (const float*)d_in[5];
    const float* bq     = (const float*)d_in[6];
    const float* wk     = (const float*)d_in[7];
    const float* wv     = (const float*)d_in[8];
    const float* bv     = (const float*)d_in[9];
    const float* wo     = (const float*)d_in[10];
    const float* bo     = (const float*)d_in[11];
    const float* ln2_w  = (const float*)d_in[12];
    const float* ln2_b  = (const float*)d_in[13];
    const float* w1g    = (const float*)d_in[14];
    const float* b1g    = (const float*)d_in[15];
    const float* w1x    = (const float*)d_in[16];
    const float* b1x    = (const float*)d_in[17];
    const float* lnm_w  = (const float*)d_in[18];
    const float* lnm_b  = (const float*)d_in[19];
    const float* w2     = (const float*)d_in[20];
    const float* b2     = (const float*)d_in[21];
    float* h = (float*)d_out;

    float *qkv, *gu, *bqkv, *b1;
    __half *yhh, *yhl, *ohh, *ohl, *mhh, *mhl;
    __half *wqkvh, *wqkvl, *woh, *wol, *w1h, *w1l, *w2h, *w2l;
    cudaGetSymbolAddress((void**)&qkv,   g_qkv);
    cudaGetSymbolAddress((void**)&gu,    g_gu);
    cudaGetSymbolAddress((void**)&bqkv,  g_bqkv);
    cudaGetSymbolAddress((void**)&b1,    g_b1);
    cudaGetSymbolAddress((void**)&yhh,   g_yh_hi);
    cudaGetSymbolAddress((void**)&yhl,   g_yh_lo);
    cudaGetSymbolAddress((void**)&ohh,   g_oh_hi);
    cudaGetSymbolAddress((void**)&ohl,   g_oh_lo);
    cudaGetSymbolAddress((void**)&mhh,   g_mh_hi);
    cudaGetSymbolAddress((void**)&mhl,   g_mh_lo);
    cudaGetSymbolAddress((void**)&wqkvh, g_wqkv_hi);
    cudaGetSymbolAddress((void**)&wqkvl, g_wqkv_lo);
    cudaGetSymbolAddress((void**)&woh,   g_wo_hi);
    cudaGetSymbolAddress((void**)&wol,   g_wo_lo);
    cudaGetSymbolAddress((void**)&w1h,   g_w1_hi);
    cudaGetSymbolAddress((void**)&w1l,   g_w1_lo);
    cudaGetSymbolAddress((void**)&w2h,   g_w2_hi);
    cudaGetSymbolAddress((void**)&w2l,   g_w2_lo);

    cudaFuncSetAttribute((const void*)gemm_mma<true>,
                         cudaFuncAttributeMaxDynamicSharedMemorySize, GEMM_SMEM);
    cudaFuncSetAttribute((const void*)gemm_mma<false>,
                         cudaFuncAttributeMaxDynamicSharedMemorySize, GEMM_SMEM);
    cudaFuncSetAttribute((const void*)attn_kernel,
                         cudaFuncAttributeMaxDynamicSharedMemorySize,
                         2 * KVT * HD * (int)sizeof(float));

    /* ---- fused weight split + packing ---- */
    {
        const int nD = DIM*DIM, nH = HIDDEN*DIM;
        CvtArgs a;
        const float* srcs[7] = { wq, wk, wv, wo, w1g, w1x, w2 };
        __half* his[7] = { wqkvh, wqkvh, wqkvh, woh, w1h, w1h, w2h };
        __half* los[7] = { wqkvl, wqkvl, wqkvl, wol, w1l, w1l, w2l };
        int lrs[7]   = { nD, nD, nD, nD, nH, nH, nH };
        int ltots[7] = { QS*DIM, QS*DIM, QS*DIM, nD, GUS*DIM, GUS*DIM, nH };
        int offs[7]  = { 0, nD, 2*nD, 0, 0, nH, 0 };
        int cum = 0;
        for (int s = 0; s < 7; s++) {
            a.src[s] = srcs[s]; a.hi[s] = his[s]; a.lo[s] = los[s];
            a.lr[s] = lrs[s]; a.ltot[s] = ltots[s]; a.off[s] = offs[s];
            a.cum[s] = cum;
            cum += DEPTH * lrs[s] / 4;
        }
        a.cum[7] = cum;
        cvt_all<<<(cum + 255)/256, 256>>>(a, cum);
        pack_bias_qkv<<<(DEPTH*QS + 255)/256, 256>>>(bq, bv, bqkv);
        pack_bias_mlp<<<(DEPTH*GUS + 255)/256, 256>>>(b1g, b1x, b1);
    }

    add_pos_kernel<<<(TOKENS*DIM + 255)/256, 256>>>(x, pos, h);

    dim3 gQKV(QS/256,  TOKENS/128);   /* (9, 32)  */
    dim3 gMLP(GUS/256, TOKENS/128);   /* (16, 32) */
    dim3 gO  (DIM/256, TOKENS/128);   /* (3, 32)  */

    for (int l = 0; l < DEPTH; l++) {
        size_t oqkv = (size_t)l * QS * DIM;
        size_t owo  = (size_t)l * DIM * DIM;
        size_t ow1  = (size_t)l * GUS * DIM;
        size_t ow2  = (size_t)l * DIM * HIDDEN;

        /* ---- attention ---- */
        ln_kernel<<<TOKENS, 256>>>(h, ln1_w + l*DIM, ln1_b + l*DIM, yhh, yhl, DIM);
        gemm_mma<true><<<gQKV, 256, GEMM_SMEM>>>(
            yhh, yhl, wqkvh + oqkv, wqkvl + oqkv,
            bqkv + l*QS, nullptr, qkv, rope, TOKENS, QS, DIM);
        attn_kernel<<<BATCH*HEADS*2, 256, 2*KVT*HD*sizeof(float)>>>(qkv, ohh, ohl);
        gemm_mma<false><<<gO, 256, GEMM_SMEM>>>(
            ohh, ohl, woh + owo, wol + owo,
            bo + l*DIM, h, h, nullptr, TOKENS, DIM, DIM);

        /* ---- SwiGLU MLP ---- */
        ln_kernel<<<TOKENS, 256>>>(h, ln2_w + l*DIM, ln2_b + l*DIM, yhh, yhl, DIM);
        gemm_mma<false><<<gMLP, 256, GEMM_SMEM>>>(
            yhh, yhl, w1h + ow1, w1l + ow1,
            b1 + l*GUS, nullptr, gu, nullptr, TOKENS, GUS, DIM);
        mlp_act_ln_kernel<<<TOKENS, 256>>>(gu, lnm_w + l*HIDDEN, lnm_b + l*HIDDEN, mhh, mhl);
        gemm_mma<false><<<gO, 256, GEMM_SMEM>>>(
            mhh, mhl, w2h + ow2, w2l + ow2,
            b2 + l*DIM, h, h, nullptr, TOKENS, DIM, HIDDEN);
    }
}

// round 8
// speedup vs baseline: 1.1583x; 1.0976x over previous
#include <cuda_runtime.h>
#include <cuda_fp16.h>
#include <math.h>
#include <stdint.h>

#define DEPTH   12
#define BATCH   16
#define NTOK    256
#define TOKENS  (BATCH*NTOK)     /* 4096 */
#define DIM     768
#define HEADS   12
#define HD      64
#define HIDDEN  2048
#define EPSF    1e-5f
#define QS      2304             /* packed qkv row stride */
#define GUS     4096             /* packed g|u row stride */

/* ------------------------------------------------------------------ */
/* Scratch buffers                                                     */
/* ------------------------------------------------------------------ */
__device__ float  g_qkv[TOKENS*QS];
__device__ float  g_gu[TOKENS*GUS];
__device__ float  g_part[3*TOKENS*DIM];     /* split-K partials */
__device__ __half g_yh_hi[TOKENS*DIM];
__device__ __half g_yh_lo[TOKENS*DIM];
__device__ __half g_oh_hi[TOKENS*DIM];
__device__ __half g_oh_lo[TOKENS*DIM];
__device__ __half g_mh_hi[TOKENS*HIDDEN];
__device__ __half g_mh_lo[TOKENS*HIDDEN];

/* packed split weights */
__device__ __half g_wqkv_hi[DEPTH*QS*DIM];
__device__ __half g_wqkv_lo[DEPTH*QS*DIM];
__device__ __half g_wo_hi[DEPTH*DIM*DIM];
__device__ __half g_wo_lo[DEPTH*DIM*DIM];
__device__ __half g_w1_hi[DEPTH*GUS*DIM];
__device__ __half g_w1_lo[DEPTH*GUS*DIM];
__device__ __half g_w2_hi[DEPTH*DIM*HIDDEN];
__device__ __half g_w2_lo[DEPTH*DIM*HIDDEN];
__device__ float  g_bqkv[DEPTH*QS];
__device__ float  g_b1[DEPTH*GUS];

/* ------------------------------------------------------------------ */
/* PTX helpers (baseline sm_80+ only)                                  */
/* ------------------------------------------------------------------ */
__device__ __forceinline__ uint32_t smem_u32(const void* p) {
    uint32_t a;
    asm("{ .reg .u64 t; cvta.to.shared.u64 t, %1; cvt.u32.u64 %0, t; }"
        : "=r"(a) : "l"(p));
    return a;
}
__device__ __forceinline__ void cp16(uint32_t dst, const void* src) {
    asm volatile("cp.async.cg.shared.global [%0], [%1], 16;"
                 :: "r"(dst), "l"(src) : "memory");
}
__device__ __forceinline__ void cp_commit() {
    asm volatile("cp.async.commit_group;" ::: "memory");
}
template<int NWAIT>
__device__ __forceinline__ void cp_wait() {
    asm volatile("cp.async.wait_group %0;" :: "n"(NWAIT) : "memory");
}
__device__ __forceinline__ void ldmx4(uint32_t& r0, uint32_t& r1,
                                      uint32_t& r2, uint32_t& r3, uint32_t a) {
    asm volatile("ldmatrix.sync.aligned.m8n8.x4.shared.b16 {%0,%1,%2,%3}, [%4];"
                 : "=r"(r0), "=r"(r1), "=r"(r2), "=r"(r3) : "r"(a));
}
__device__ __forceinline__ void mma16816(float* c, const uint32_t* a,
                                         uint32_t b0, uint32_t b1) {
    asm("mma.sync.aligned.m16n8k16.row.col.f32.f16.f16.f32 "
        "{%0,%1,%2,%3}, {%4,%5,%6,%7}, {%8,%9}, {%0,%1,%2,%3};"
        : "+f"(c[0]), "+f"(c[1]), "+f"(c[2]), "+f"(c[3])
        : "r"(a[0]), "r"(a[1]), "r"(a[2]), "r"(a[3]), "r"(b0), "r"(b1));
}

/* ------------------------------------------------------------------ */
/* Split-fp16 HMMA GEMM (NT): C = Ahi*Bhi + Ahi*Blo + Alo*Bhi          */
/* CTA tile 128x256, 8 warps of 64x64 (2x4), BK=64, double-buffered.   */
/* PARTIAL: blockIdx.z selects K-range, writes raw partials.           */
/* ------------------------------------------------------------------ */
#define PA 16384
#define PB 32768
#define BUFSZ (2*PA + 2*PB)            /* 98304 */
#define GEMM_SMEM (2*BUFSZ)            /* 196608 */

template<bool ROPE, bool PARTIAL>
__global__ void __launch_bounds__(256, 1) gemm_mma(
    const __half* __restrict__ Ahi, const __half* __restrict__ Alo,
    const __half* __restrict__ Bhi, const __half* __restrict__ Blo,
    const float* __restrict__ bias, const float* __restrict__ res,
    float* __restrict__ C, const float* __restrict__ remb,
    int M, int N, int K) {
    extern __shared__ __align__(128) char smem[];
    uint32_t sb = smem_u32(smem);
    int tid = threadIdx.x, wid = tid >> 5, lane = tid & 31;
    int wm = wid >> 2, wn = wid & 3;
    int bm = blockIdx.y * 128, bn = blockIdx.x * 256;

    int l15 = lane & 15, kg = lane >> 4;
    uint32_t arow = (uint32_t)(wm * 64 + l15);
    uint32_t brow = (uint32_t)(wn * 64 + l15);
    int aswz = (int)(arow & 7), bswz = (int)(brow & 7);

    float acc[4][8][4];
    #pragma unroll
    for (int i = 0; i < 4; i++)
        #pragma unroll
        for (int j = 0; j < 8; j++)
            #pragma unroll
            for (int e = 0; e < 4; e++) acc[i][j][e] = 0.f;

    int nch = K >> 6;
    int c0 = 0, c1 = nch;
    if (PARTIAL) {
        int z = blockIdx.z;
        c0 = (z * nch) / 3;
        c1 = ((z + 1) * nch) / 3;
    }

    auto load_chunk = [&](uint32_t dst, int ko) {
        #pragma unroll
        for (int j = 0; j < 4; j++) {
            int id = tid + j * 256;
            int row = id >> 3, g = id & 7;
            uint32_t off = (uint32_t)row * 128u + (uint32_t)((g ^ (row & 7)) * 16);
            size_t so = (size_t)(bm + row) * K + ko + g * 8;
            cp16(dst + off,      Ahi + so);
            cp16(dst + PA + off, Alo + so);
        }
        #pragma unroll
        for (int j = 0; j < 8; j++) {
            int id = tid + j * 256;
            int row = id >> 3, g = id & 7;
            uint32_t off = (uint32_t)row * 128u + (uint32_t)((g ^ (row & 7)) * 16);
            size_t so = (size_t)(bn + row) * K + ko + g * 8;
            cp16(dst + 2*PA + off,      Bhi + so);
            cp16(dst + 2*PA + PB + off, Blo + so);
        }
    };

    load_chunk(sb, c0 * 64);
    cp_commit();

    for (int c = c0; c < c1; c++) {
        if (c + 1 < c1) {
            load_chunk(sb + (uint32_t)(((c - c0 + 1) & 1) * BUFSZ), (c + 1) * 64);
            cp_commit();
            cp_wait<1>();
        } else {
            cp_wait<0>();
        }
        __syncthreads();

        uint32_t ba = sb + (uint32_t)(((c - c0) & 1) * BUFSZ);
        uint32_t a_hi = ba             + arow * 128u;
        uint32_t a_lo = ba + PA        + arow * 128u;
        uint32_t b_hi = ba + 2*PA      + brow * 128u;
        uint32_t b_lo = ba + 2*PA + PB + brow * 128u;

        #pragma unroll
        for (int ks = 0; ks < 4; ks++) {
            int g = ks * 2 + kg;
            uint32_t goff = (uint32_t)((g ^ aswz) * 16);
            uint32_t gofb = (uint32_t)((g ^ bswz) * 16);
            uint32_t afh[4][4], afl[4][4], bfh[4][4], bfl[4][4];
            #pragma unroll
            for (int mf = 0; mf < 4; mf++) {
                ldmx4(afh[mf][0], afh[mf][1], afh[mf][2], afh[mf][3],
                      a_hi + (uint32_t)(mf * 2048) + goff);
                ldmx4(afl[mf][0], afl[mf][1], afl[mf][2], afl[mf][3],
                      a_lo + (uint32_t)(mf * 2048) + goff);
            }
            #pragma unroll
            for (int nf2 = 0; nf2 < 4; nf2++) {
                ldmx4(bfh[nf2][0], bfh[nf2][1], bfh[nf2][2], bfh[nf2][3],
                      b_hi + (uint32_t)(nf2 * 2048) + gofb);
                ldmx4(bfl[nf2][0], bfl[nf2][1], bfl[nf2][2], bfl[nf2][3],
                      b_lo + (uint32_t)(nf2 * 2048) + gofb);
            }
            #pragma unroll
            for (int mf = 0; mf < 4; mf++)
                #pragma unroll
                for (int nf = 0; nf < 8; nf++)
                    mma16816(acc[mf][nf], afh[mf],
                             bfh[nf >> 1][nf & 1], bfh[nf >> 1][(nf & 1) + 2]);
            #pragma unroll
            for (int mf = 0; mf < 4; mf++)
                #pragma unroll
                for (int nf = 0; nf < 8; nf++)
                    mma16816(acc[mf][nf], afh[mf],
                             bfl[nf >> 1][nf & 1], bfl[nf >> 1][(nf & 1) + 2]);
            #pragma unroll
            for (int mf = 0; mf < 4; mf++)
                #pragma unroll
                for (int nf = 0; nf < 8; nf++)
                    mma16816(acc[mf][nf], afl[mf],
                             bfh[nf >> 1][nf & 1], bfh[nf >> 1][(nf & 1) + 2]);
        }
        __syncthreads();
    }

    int r0 = lane >> 2, cb = (lane & 3) * 2;
    if (PARTIAL) {
        float* Cp = C + (size_t)blockIdx.z * M * N;
        #pragma unroll
        for (int mf = 0; mf < 4; mf++)
            #pragma unroll
            for (int nf = 0; nf < 8; nf++) {
                int n0 = bn + wn * 64 + nf * 8 + cb;
                #pragma unroll
                for (int half = 0; half < 2; half++) {
                    int m0 = bm + wm * 64 + mf * 16 + r0 + half * 8;
                    *(float2*)(Cp + (size_t)m0 * N + n0) =
                        make_float2(acc[mf][nf][half * 2], acc[mf][nf][half * 2 + 1]);
                }
            }
        return;
    }
    #pragma unroll
    for (int mf = 0; mf < 4; mf++) {
        #pragma unroll
        for (int nf = 0; nf < 8; nf++) {
            int n0 = bn + wn * 64 + nf * 8 + cb;
            float bz0 = bias ? bias[n0]     : 0.f;
            float bz1 = bias ? bias[n0 + 1] : 0.f;
            #pragma unroll
            for (int half = 0; half < 2; half++) {
                int m0 = bm + wm * 64 + mf * 16 + r0 + half * 8;
                float v0 = acc[mf][nf][half * 2]     + bz0;
                float v1 = acc[mf][nf][half * 2 + 1] + bz1;
                if (ROPE) {
                    if (n0 < 2*DIM) {
                        int pos = m0 & (NTOK - 1);
                        int d   = n0 & (HD - 1);
                        const float* e = remb + pos * (2*HD);
                        float2 sn = *(const float2*)(e + d);
                        float2 cs = *(const float2*)(e + HD + d);
                        float t0 = v0 * cs.x - v1 * sn.x;
                        float t1 = v1 * cs.y + v0 * sn.y;
                        v0 = t0; v1 = t1;
                    }
                }
                size_t idx = (size_t)m0 * N + n0;
                if (res) { v0 += res[idx]; v1 += res[idx + 1]; }
                *(float2*)(C + idx) = make_float2(v0, v1);
            }
        }
    }
}

/* ------------------------------------------------------------------ */
/* reduce3: h += bias + p0 + p1 + p2 (fixed order, deterministic)      */
/* ------------------------------------------------------------------ */
__global__ void reduce3(float* __restrict__ h, const float* __restrict__ part,
                        const float* __restrict__ bias) {
    int i = blockIdx.x * blockDim.x + threadIdx.x;
    if (i >= TOKENS*DIM/4) return;
    float4 a  = ((const float4*)h)[i];
    float4 p0 = ((const float4*)part)[i];
    float4 p1 = ((const float4*)(part + TOKENS*DIM))[i];
    float4 p2 = ((const float4*)(part + 2*TOKENS*DIM))[i];
    float4 bz = *(const float4*)(bias + (i*4) % DIM);
    a.x += bz.x + ((p0.x + p1.x) + p2.x);
    a.y += bz.y + ((p0.y + p1.y) + p2.y);
    a.z += bz.z + ((p0.z + p1.z) + p2.z);
    a.w += bz.w + ((p0.w + p1.w) + p2.w);
    ((float4*)h)[i] = a;
}

/* ------------------------------------------------------------------ */
/* Single fused fp32 -> (hi, lo) split+pack for ALL weights            */
/* ------------------------------------------------------------------ */
struct CvtArgs {
    const float* src[7];
    __half* hi[7];
    __half* lo[7];
    int lr[7];
    int ltot[7];
    int off[7];
    int cum[8];
};
__device__ __forceinline__ void split2(float a, float b, __half2& h, __half2& l) {
    __half ha = __float2half_rn(a), hb = __float2half_rn(b);
    __half la = __float2half_rn(a - __half2float(ha));
    __half lb = __float2half_rn(b - __half2float(hb));
    h = __halves2half2(ha, hb);
    l = __halves2half2(la, lb);
}
__global__ void cvt_all(CvtArgs a, int total4) {
    int i4 = blockIdx.x * blockDim.x + threadIdx.x;
    if (i4 >= total4) return;
    int s = 0;
    #pragma unroll
    for (int j = 1; j < 7; j++) s += (i4 >= a.cum[j]);
    int i = (i4 - a.cum[s]) * 4;
    int l = i / a.lr[s];
    int rem = i - l * a.lr[s];
    size_t d = (size_t)l * a.ltot[s] + a.off[s] + rem;
    float4 v = *(const float4*)(a.src[s] + i);
    __half2 h0, l0, h1, l1;
    split2(v.x, v.y, h0, l0);
    split2(v.z, v.w, h1, l1);
    ((__half2*)(a.hi[s] + d))[0] = h0; ((__half2*)(a.hi[s] + d))[1] = h1;
    ((__half2*)(a.lo[s] + d))[0] = l0; ((__half2*)(a.lo[s] + d))[1] = l1;
}

/* ------------------------------------------------------------------ */
/* add_pos + bias packing fused (keeps gemm at ncu capture slot)       */
/* ------------------------------------------------------------------ */
__global__ void add_pos_prep(const float* __restrict__ x,
                             const float* __restrict__ pos,
                             float* __restrict__ h,
                             const float* __restrict__ bq,
                             const float* __restrict__ bv,
                             float* __restrict__ bqkv,
                             const float* __restrict__ bg,
                             const float* __restrict__ bx,
                             float* __restrict__ b1) {
    int idx = blockIdx.x * blockDim.x + threadIdx.x;
    if (idx < TOKENS*DIM) h[idx] = x[idx] + pos[idx % (NTOK*DIM)];
    if (idx < DEPTH*QS) {
        int l = idx / QS, c = idx % QS;
        bqkv[idx] = c < DIM ? bq[l*DIM + c]
                  : (c < 2*DIM ? 0.f : bv[l*DIM + c - 2*DIM]);
    }
    if (idx < DEPTH*GUS) {
        int l = idx / GUS, c = idx % GUS;
        b1[idx] = c < HIDDEN ? bg[l*HIDDEN + c] : bx[l*HIDDEN + c - HIDDEN];
    }
}

/* ------------------------------------------------------------------ */
/* Block reduction (256 threads)                                       */
/* ------------------------------------------------------------------ */
__device__ __forceinline__ float2 block_reduce_2(float s, float s2) {
    __shared__ float red[16];
    #pragma unroll
    for (int o = 16; o > 0; o >>= 1) {
        s  += __shfl_down_sync(0xffffffffu, s,  o);
        s2 += __shfl_down_sync(0xffffffffu, s2, o);
    }
    int w = threadIdx.x >> 5, l = threadIdx.x & 31;
    if (l == 0) { red[w] = s; red[8 + w] = s2; }
    __syncthreads();
    if (threadIdx.x < 32) {
        s  = (l < 8) ? red[l]     : 0.f;
        s2 = (l < 8) ? red[8 + l] : 0.f;
        #pragma unroll
        for (int o = 4; o > 0; o >>= 1) {
            s  += __shfl_down_sync(0xffffffffu, s,  o);
            s2 += __shfl_down_sync(0xffffffffu, s2, o);
        }
        if (l == 0) { red[0] = s; red[1] = s2; }
    }
    __syncthreads();
    return make_float2(red[0], red[1]);
}

__device__ __forceinline__ uint32_t pack_h2(float a, float b) {
    __half2 h = __floats2half2_rn(a, b);
    return *(uint32_t*)&h;
}

/* ------------------------------------------------------------------ */
/* LayerNorm over DIM (vectorized, fp32 in, split fp16 out)            */
/* ------------------------------------------------------------------ */
__global__ void __launch_bounds__(256) ln_kernel(
    const float* __restrict__ x, const float* __restrict__ w,
    const float* __restrict__ b, __half* __restrict__ ohi,
    __half* __restrict__ olo) {
    int t = blockIdx.x;
    int c4 = threadIdx.x;                 /* 0..255, active < 192 */
    float4 v = make_float4(0.f, 0.f, 0.f, 0.f);
    if (c4 < DIM/4) v = ((const float4*)(x + (size_t)t * DIM))[c4];
    float s  = v.x + v.y + v.z + v.w;
    float s2 = v.x*v.x + v.y*v.y + v.z*v.z + v.w*v.w;
    float2 r = block_reduce_2(s, s2);
    float mean = r.x / DIM;
    float var  = r.y / DIM - mean * mean;
    float inv  = rsqrtf(var + EPSF);
    if (c4 < DIM/4) {
        float4 wv = ((const float4*)w)[c4];
        float4 bv = ((const float4*)b)[c4];
        float y0 = (v.x - mean) * inv * wv.x + bv.x;
        float y1 = (v.y - mean) * inv * wv.y + bv.y;
        float y2 = (v.z - mean) * inv * wv.z + bv.z;
        float y3 = (v.w - mean) * inv * wv.w + bv.w;
        __half h0 = __float2half_rn(y0), h1 = __float2half_rn(y1);
        __half h2 = __float2half_rn(y2), h3 = __float2half_rn(y3);
        uint2 hi = make_uint2(pack_h2(y0, y1), pack_h2(y2, y3));
        uint2 lo = make_uint2(pack_h2(y0 - __half2float(h0), y1 - __half2float(h1)),
                              pack_h2(y2 - __half2float(h2), y3 - __half2float(h3)));
        ((uint2*)ohi)[(size_t)t * (DIM/4) + c4] = hi;
        ((uint2*)olo)[(size_t)t * (DIM/4) + c4] = lo;
    }
}

/* ------------------------------------------------------------------ */
/* silu(g)*u then LN over HIDDEN (register-resident, vectorized)       */
/* ------------------------------------------------------------------ */
__global__ void __launch_bounds__(256) mlp_act_ln_kernel(
    const float* __restrict__ gu,
    const float* __restrict__ w, const float* __restrict__ b,
    __half* __restrict__ ohi, __half* __restrict__ olo) {
    int t = blockIdx.x;
    const float* gr = gu + (size_t)t * GUS;
    const float* ur = gr + HIDDEN;
    float a[8];
    float s = 0.f, s2 = 0.f;
    #pragma unroll
    for (int j = 0; j < 2; j++) {
        int c4 = threadIdx.x + j * 256;
        float4 gv = ((const float4*)gr)[c4];
        float4 uv = ((const float4*)ur)[c4];
        float* aj = a + j * 4;
        aj[0] = gv.x / (1.f + __expf(-gv.x)) * uv.x;
        aj[1] = gv.y / (1.f + __expf(-gv.y)) * uv.y;
        aj[2] = gv.z / (1.f + __expf(-gv.z)) * uv.z;
        aj[3] = gv.w / (1.f + __expf(-gv.w)) * uv.w;
        s  += aj[0] + aj[1] + aj[2] + aj[3];
        s2 += aj[0]*aj[0] + aj[1]*aj[1] + aj[2]*aj[2] + aj[3]*aj[3];
    }
    float2 r = block_reduce_2(s, s2);
    float mean = r.x / HIDDEN;
    float var  = r.y / HIDDEN - mean * mean;
    float inv  = rsqrtf(var + EPSF);
    #pragma unroll
    for (int j = 0; j < 2; j++) {
        int c4 = threadIdx.x + j * 256;
        float4 wv = ((const float4*)w)[c4];
        float4 bv = ((const float4*)b)[c4];
        float* aj = a + j * 4;
        float y0 = (aj[0] - mean) * inv * wv.x + bv.x;
        float y1 = (aj[1] - mean) * inv * wv.y + bv.y;
        float y2 = (aj[2] - mean) * inv * wv.z + bv.z;
        float y3 = (aj[3] - mean) * inv * wv.w + bv.w;
        __half h0 = __float2half_rn(y0), h1 = __float2half_rn(y1);
        __half h2 = __float2half_rn(y2), h3 = __float2half_rn(y3);
        uint2 hi = make_uint2(pack_h2(y0, y1), pack_h2(y2, y3));
        uint2 lo = make_uint2(pack_h2(y0 - __half2float(h0), y1 - __half2float(h1)),
                              pack_h2(y2 - __half2float(h2), y3 - __half2float(h3)));
        ((uint2*)ohi)[(size_t)t * (HIDDEN/4) + c4] = hi;
        ((uint2*)olo)[(size_t)t * (HIDDEN/4) + c4] = lo;
    }
}

/* ------------------------------------------------------------------ */
/* Attention: 2 lanes per query row (32-dim slices), KV tiled x128.    */
/* ------------------------------------------------------------------ */
#define KVT 128
__global__ void __launch_bounds__(256) attn_kernel(
    const float* __restrict__ qkv, __half* __restrict__ ohi,
    __half* __restrict__ olo) {
    extern __shared__ float sm[];
    float* Ks = sm;
    float* Vs = sm + KVT * HD;
    int blk = blockIdx.x;
    int half_blk = blk & 1;
    int bh = blk >> 1;
    int b  = bh / HEADS, h = bh % HEADS;
    size_t base_q = (size_t)(b * NTOK) * QS + h * HD;
    int tid = threadIdx.x, lane = tid & 31, wid = tid >> 5;
    int row_local = wid * 16 + (lane & 15);
    int part = lane >> 4;
    int i = half_blk * 128 + row_local;

    const float scale = 0.125f;
    float qreg[32];
    {
        const float* qp = qkv + base_q + (size_t)i * QS + part * 32;
        #pragma unroll
        for (int d = 0; d < 32; d++) qreg[d] = qp[d] * scale;
    }

    float mrun = -1e30f, lrun = 0.f;
    float accv[32];
    #pragma unroll
    for (int d = 0; d < 32; d++) accv[d] = 0.f;

    for (int tkv = 0; tkv < NTOK / KVT; tkv++) {
        for (int idx = tid; idx < KVT * HD; idx += 256) {
            int row = idx >> 6, col = idx & 63;
            size_t src = base_q + (size_t)(tkv * KVT + row) * QS + col;
            Ks[idx] = qkv[src + DIM];
            Vs[idx] = qkv[src + 2*DIM];
        }
        __syncthreads();

        for (int j = 0; j < KVT; j++) {
            const float* kr = Ks + j * HD + part * 32;
            float s = 0.f;
            #pragma unroll
            for (int d = 0; d < 32; d++) s += qreg[d] * kr[d];
            s += __shfl_xor_sync(0xffffffffu, s, 16);
            float mnew = fmaxf(mrun, s);
            float cc = __expf(mrun - mnew);
            float p  = __expf(s - mnew);
            lrun = lrun * cc + p;
            const float* vr = Vs + j * HD + part * 32;
            #pragma unroll
            for (int d = 0; d < 32; d++) accv[d] = accv[d] * cc + p * vr[d];
            mrun = mnew;
        }
        __syncthreads();
    }

    float inv = 1.f / lrun;
    size_t ob = (size_t)(b * NTOK + i) * DIM + h * HD + part * 32;
    #pragma unroll
    for (int d = 0; d < 32; d++) {
        float v0 = accv[d] * inv;
        __half hh = __float2half_rn(v0);
        ohi[ob + d] = hh;
        olo[ob + d] = __float2half_rn(v0 - __half2float(hh));
    }
}

/* ------------------------------------------------------------------ */
/* Launch                                                              */
/* ------------------------------------------------------------------ */
extern "C" void kernel_launch(void* const* d_in, const int* in_sizes, int n_in,
                              void* d_out, int out_size) {
    const float* x      = (const float*)d_in[0];
    const float* pos    = (const float*)d_in[1];
    const float* rope   = (const float*)d_in[2];
    const float* ln1_w  = (const float*)d_in[3];
    const float* ln1_b  = (const float*)d_in[4];
    const float* wq     = (const float*)d_in[5];
    const float* bq     = (const float*)d_in[6];
    const float* wk     = (const float*)d_in[7];
    const float* wv     = (const float*)d_in[8];
    const float* bv     = (const float*)d_in[9];
    const float* wo     = (const float*)d_in[10];
    const float* bo     = (const float*)d_in[11];
    const float* ln2_w  = (const float*)d_in[12];
    const float* ln2_b  = (const float*)d_in[13];
    const float* w1g    = (const float*)d_in[14];
    const float* b1g    = (const float*)d_in[15];
    const float* w1x    = (const float*)d_in[16];
    const float* b1x    = (const float*)d_in[17];
    const float* lnm_w  = (const float*)d_in[18];
    const float* lnm_b  = (const float*)d_in[19];
    const float* w2     = (const float*)d_in[20];
    const float* b2     = (const float*)d_in[21];
    float* h = (float*)d_out;

    float *qkv, *gu, *bqkv, *b1, *part;
    __half *yhh, *yhl, *ohh, *ohl, *mhh, *mhl;
    __half *wqkvh, *wqkvl, *woh, *wol, *w1h, *w1l, *w2h, *w2l;
    cudaGetSymbolAddress((void**)&qkv,   g_qkv);
    cudaGetSymbolAddress((void**)&gu,    g_gu);
    cudaGetSymbolAddress((void**)&part,  g_part);
    cudaGetSymbolAddress((void**)&bqkv,  g_bqkv);
    cudaGetSymbolAddress((void**)&b1,    g_b1);
    cudaGetSymbolAddress((void**)&yhh,   g_yh_hi);
    cudaGetSymbolAddress((void**)&yhl,   g_yh_lo);
    cudaGetSymbolAddress((void**)&ohh,   g_oh_hi);
    cudaGetSymbolAddress((void**)&ohl,   g_oh_lo);
    cudaGetSymbolAddress((void**)&mhh,   g_mh_hi);
    cudaGetSymbolAddress((void**)&mhl,   g_mh_lo);
    cudaGetSymbolAddress((void**)&wqkvh, g_wqkv_hi);
    cudaGetSymbolAddress((void**)&wqkvl, g_wqkv_lo);
    cudaGetSymbolAddress((void**)&woh,   g_wo_hi);
    cudaGetSymbolAddress((void**)&wol,   g_wo_lo);
    cudaGetSymbolAddress((void**)&w1h,   g_w1_hi);
    cudaGetSymbolAddress((void**)&w1l,   g_w1_lo);
    cudaGetSymbolAddress((void**)&w2h,   g_w2_hi);
    cudaGetSymbolAddress((void**)&w2l,   g_w2_lo);

    cudaFuncSetAttribute((const void*)gemm_mma<true,false>,
                         cudaFuncAttributeMaxDynamicSharedMemorySize, GEMM_SMEM);
    cudaFuncSetAttribute((const void*)gemm_mma<false,false>,
                         cudaFuncAttributeMaxDynamicSharedMemorySize, GEMM_SMEM);
    cudaFuncSetAttribute((const void*)gemm_mma<false,true>,
                         cudaFuncAttributeMaxDynamicSharedMemorySize, GEMM_SMEM);
    cudaFuncSetAttribute((const void*)attn_kernel,
                         cudaFuncAttributeMaxDynamicSharedMemorySize,
                         2 * KVT * HD * (int)sizeof(float));

    /* ---- [1] fused weight split + pack ---- */
    {
        const int nD = DIM*DIM, nH = HIDDEN*DIM;
        CvtArgs a;
        const float* srcs[7] = { wq, wk, wv, wo, w1g, w1x, w2 };
        __half* his[7] = { wqkvh, wqkvh, wqkvh, woh, w1h, w1h, w2h };
        __half* los[7] = { wqkvl, wqkvl, wqkvl, wol, w1l, w1l, w2l };
        int lrs[7]   = { nD, nD, nD, nD, nH, nH, nH };
        int ltots[7] = { QS*DIM, QS*DIM, QS*DIM, nD, GUS*DIM, GUS*DIM, nH };
        int offs[7]  = { 0, nD, 2*nD, 0, 0, nH, 0 };
        int cum = 0;
        for (int s = 0; s < 7; s++) {
            a.src[s] = srcs[s]; a.hi[s] = his[s]; a.lo[s] = los[s];
            a.lr[s] = lrs[s]; a.ltot[s] = ltots[s]; a.off[s] = offs[s];
            a.cum[s] = cum;
            cum += DEPTH * lrs[s] / 4;
        }
        a.cum[7] = cum;
        cvt_all<<<(cum + 255)/256, 256>>>(a, cum);
    }
    /* ---- [2] pos-embed add + bias packing ---- */
    add_pos_prep<<<(TOKENS*DIM + 255)/256, 256>>>(x, pos, h, bq, bv, bqkv,
                                                  b1g, b1x, b1);

    dim3 gQKV(QS/256,  TOKENS/128);      /* (9, 32)    */
    dim3 gMLP(GUS/256, TOKENS/128);      /* (16, 32)   */
    dim3 gSK (DIM/256, TOKENS/128, 3);   /* (3, 32, 3) */
    const int RED = (TOKENS*DIM/4 + 255)/256;

    for (int l = 0; l < DEPTH; l++) {
        size_t oqkv = (size_t)l * QS * DIM;
        size_t owo  = (size_t)l * DIM * DIM;
        size_t ow1  = (size_t)l * GUS * DIM;
        size_t ow2  = (size_t)l * DIM * HIDDEN;

        /* ---- attention ---- */
        ln_kernel<<<TOKENS, 256>>>(h, ln1_w + l*DIM, ln1_b + l*DIM, yhh, yhl);
        gemm_mma<true,false><<<gQKV, 256, GEMM_SMEM>>>(
            yhh, yhl, wqkvh + oqkv, wqkvl + oqkv,
            bqkv + l*QS, nullptr, qkv, rope, TOKENS, QS, DIM);
        attn_kernel<<<BATCH*HEADS*2, 256, 2*KVT*HD*sizeof(float)>>>(qkv, ohh, ohl);
        gemm_mma<false,true><<<gSK, 256, GEMM_SMEM>>>(
            ohh, ohl, woh + owo, wol + owo,
            nullptr, nullptr, part, nullptr, TOKENS, DIM, DIM);
        reduce3<<<RED, 256>>>(h, part, bo + l*DIM);

        /* ---- SwiGLU MLP ---- */
        ln_kernel<<<TOKENS, 256>>>(h, ln2_w + l*DIM, ln2_b + l*DIM, yhh, yhl);
        gemm_mma<false,false><<<gMLP, 256, GEMM_SMEM>>>(
            yhh, yhl, w1h + ow1, w1l + ow1,
            b1 + l*GUS, nullptr, gu, nullptr, TOKENS, GUS, DIM);
        mlp_act_ln_kernel<<<TOKENS, 256>>>(gu, lnm_w + l*HIDDEN, lnm_b + l*HIDDEN, mhh, mhl);
        gemm_mma<false,true><<<gSK, 256, GEMM_SMEM>>>(
            mhh, mhl, w2h + ow2, w2l + ow2,
            nullptr, nullptr, part, nullptr, TOKENS, DIM, HIDDEN);
        reduce3<<<RED, 256>>>(h, part, b2 + l*DIM);
    }
}

// round 9
// speedup vs baseline: 1.1598x; 1.0013x over previous
#include <cuda_runtime.h>
#include <cuda_fp16.h>
#include <math.h>
#include <stdint.h>

#define DEPTH   12
#define BATCH   16
#define NTOK    256
#define TOKENS  (BATCH*NTOK)     /* 4096 */
#define DIM     768
#define HEADS   12
#define HD      64
#define HIDDEN  2048
#define EPSF    1e-5f
#define QS      2304             /* packed qkv row stride */
#define GUS     4096             /* packed g|u row stride */

/* ------------------------------------------------------------------ */
/* Scratch buffers                                                     */
/* ------------------------------------------------------------------ */
__device__ float  g_qkv[TOKENS*QS];
__device__ float  g_gu[TOKENS*GUS];
__device__ float  g_part[3*TOKENS*DIM];
__device__ __half g_yh_hi[TOKENS*DIM];
__device__ __half g_yh_lo[TOKENS*DIM];
__device__ __half g_oh_hi[TOKENS*DIM];
__device__ __half g_oh_lo[TOKENS*DIM];
__device__ __half g_mh_hi[TOKENS*HIDDEN];
__device__ __half g_mh_lo[TOKENS*HIDDEN];

/* packed split weights */
__device__ __half g_wqkv_hi[DEPTH*QS*DIM];
__device__ __half g_wqkv_lo[DEPTH*QS*DIM];
__device__ __half g_wo_hi[DEPTH*DIM*DIM];
__device__ __half g_wo_lo[DEPTH*DIM*DIM];
__device__ __half g_w1_hi[DEPTH*GUS*DIM];
__device__ __half g_w1_lo[DEPTH*GUS*DIM];
__device__ __half g_w2_hi[DEPTH*DIM*HIDDEN];
__device__ __half g_w2_lo[DEPTH*DIM*HIDDEN];
__device__ float  g_bqkv[DEPTH*QS];
__device__ float  g_b1[DEPTH*GUS];

/* ------------------------------------------------------------------ */
/* PTX helpers                                                         */
/* ------------------------------------------------------------------ */
__device__ __forceinline__ uint32_t smem_u32(const void* p) {
    uint32_t a;
    asm("{ .reg .u64 t; cvta.to.shared.u64 t, %1; cvt.u32.u64 %0, t; }"
        : "=r"(a) : "l"(p));
    return a;
}
__device__ __forceinline__ void cp16(uint32_t dst, const void* src) {
    asm volatile("cp.async.cg.shared.global [%0], [%1], 16;"
                 :: "r"(dst), "l"(src) : "memory");
}
__device__ __forceinline__ void cp_commit() {
    asm volatile("cp.async.commit_group;" ::: "memory");
}
template<int NWAIT>
__device__ __forceinline__ void cp_wait() {
    asm volatile("cp.async.wait_group %0;" :: "n"(NWAIT) : "memory");
}
__device__ __forceinline__ void ldmx4(uint32_t& r0, uint32_t& r1,
                                      uint32_t& r2, uint32_t& r3, uint32_t a) {
    asm volatile("ldmatrix.sync.aligned.m8n8.x4.shared.b16 {%0,%1,%2,%3}, [%4];"
                 : "=r"(r0), "=r"(r1), "=r"(r2), "=r"(r3) : "r"(a));
}
__device__ __forceinline__ void mma16816(float* c, const uint32_t* a,
                                         uint32_t b0, uint32_t b1) {
    asm("mma.sync.aligned.m16n8k16.row.col.f32.f16.f16.f32 "
        "{%0,%1,%2,%3}, {%4,%5,%6,%7}, {%8,%9}, {%0,%1,%2,%3};"
        : "+f"(c[0]), "+f"(c[1]), "+f"(c[2]), "+f"(c[3])
        : "r"(a[0]), "r"(a[1]), "r"(a[2]), "r"(a[3]), "r"(b0), "r"(b1));
}

/* ------------------------------------------------------------------ */
/* Split-fp16 HMMA GEMM (NT): C = Ahi*Bhi + Ahi*Blo + Alo*Bhi          */
/* CTA tile 128x256, 8 warps of 64x64 (2x4), BK=64, double-buffered.   */
/* Mainloop: hoisted addresses + term-sequential fragment loading.     */
/* ------------------------------------------------------------------ */
#define PA 16384
#define PB 32768
#define BUFSZ (2*PA + 2*PB)            /* 98304 */
#define GEMM_SMEM (2*BUFSZ)            /* 196608 */

template<bool ROPE, bool PARTIAL>
__global__ void __launch_bounds__(256, 1) gemm_mma(
    const __half* __restrict__ Ahi, const __half* __restrict__ Alo,
    const __half* __restrict__ Bhi, const __half* __restrict__ Blo,
    const float* __restrict__ bias, const float* __restrict__ res,
    float* __restrict__ C, const float* __restrict__ remb,
    int M, int N, int K) {
    extern __shared__ __align__(128) char smem[];
    uint32_t sb = smem_u32(smem);
    int tid = threadIdx.x, wid = tid >> 5, lane = tid & 31;
    int wm = wid >> 2, wn = wid & 3;
    int bm = blockIdx.y * 128, bn = blockIdx.x * 256;

    int l15 = lane & 15, kg = lane >> 4;
    uint32_t arow = (uint32_t)(wm * 64 + l15);
    uint32_t brow = (uint32_t)(wn * 64 + l15);
    int aswz = (int)(arow & 7), bswz = (int)(brow & 7);

    /* ---- hoisted loop-invariant addresses ---- */
    uint32_t aoff[4], boff[4];
    #pragma unroll
    for (int ks = 0; ks < 4; ks++) {
        int g = ks * 2 + kg;
        aoff[ks] = (uint32_t)((g ^ aswz) * 16);
        boff[ks] = (uint32_t)((g ^ bswz) * 16);
    }
    uint32_t aHiB[2], aLoB[2], bHiB[2], bLoB[2];
    #pragma unroll
    for (int bf = 0; bf < 2; bf++) {
        uint32_t ba = sb + (uint32_t)(bf * BUFSZ);
        aHiB[bf] = ba             + arow * 128u;
        aLoB[bf] = ba + PA        + arow * 128u;
        bHiB[bf] = ba + 2*PA      + brow * 128u;
        bLoB[bf] = ba + 2*PA + PB + brow * 128u;
    }

    float acc[4][8][4];
    #pragma unroll
    for (int i = 0; i < 4; i++)
        #pragma unroll
        for (int j = 0; j < 8; j++)
            #pragma unroll
            for (int e = 0; e < 4; e++) acc[i][j][e] = 0.f;

    int nch = K >> 6;
    int c0 = 0, c1 = nch;
    if (PARTIAL) {
        int z = blockIdx.z;
        c0 = (z * nch) / 3;
        c1 = ((z + 1) * nch) / 3;
    }

    auto load_chunk = [&](uint32_t dst, int ko) {
        #pragma unroll
        for (int j = 0; j < 4; j++) {
            int id = tid + j * 256;
            int row = id >> 3, g = id & 7;
            uint32_t off = (uint32_t)row * 128u + (uint32_t)((g ^ (row & 7)) * 16);
            size_t so = (size_t)(bm + row) * K + ko + g * 8;
            cp16(dst + off,      Ahi + so);
            cp16(dst + PA + off, Alo + so);
        }
        #pragma unroll
        for (int j = 0; j < 8; j++) {
            int id = tid + j * 256;
            int row = id >> 3, g = id & 7;
            uint32_t off = (uint32_t)row * 128u + (uint32_t)((g ^ (row & 7)) * 16);
            size_t so = (size_t)(bn + row) * K + ko + g * 8;
            cp16(dst + 2*PA + off,      Bhi + so);
            cp16(dst + 2*PA + PB + off, Blo + so);
        }
    };

    load_chunk(sb, c0 * 64);
    cp_commit();

    for (int c = c0; c < c1; c++) {
        if (c + 1 < c1) {
            load_chunk(sb + (uint32_t)(((c - c0 + 1) & 1) * BUFSZ), (c + 1) * 64);
            cp_commit();
            cp_wait<1>();
        } else {
            cp_wait<0>();
        }
        __syncthreads();

        int bufi = (c - c0) & 1;
        uint32_t a_hi = aHiB[bufi], a_lo = aLoB[bufi];
        uint32_t b_hi = bHiB[bufi], b_lo = bLoB[bufi];

        #pragma unroll
        for (int ks = 0; ks < 4; ks++) {
            uint32_t ao = aoff[ks], bo = boff[ks];
            /* term 1: Ahi * Bhi */
            uint32_t afh[4][4], bfh[4][4];
            #pragma unroll
            for (int mf = 0; mf < 4; mf++)
                ldmx4(afh[mf][0], afh[mf][1], afh[mf][2], afh[mf][3],
                      a_hi + (uint32_t)(mf * 2048) + ao);
            #pragma unroll
            for (int nf2 = 0; nf2 < 4; nf2++)
                ldmx4(bfh[nf2][0], bfh[nf2][1], bfh[nf2][2], bfh[nf2][3],
                      b_hi + (uint32_t)(nf2 * 2048) + bo);
            #pragma unroll
            for (int mf = 0; mf < 4; mf++)
                #pragma unroll
                for (int nf = 0; nf < 8; nf++)
                    mma16816(acc[mf][nf], afh[mf],
                             bfh[nf >> 1][nf & 1], bfh[nf >> 1][(nf & 1) + 2]);
            /* term 2: Ahi * Blo */
            {
                uint32_t bfl[4][4];
                #pragma unroll
                for (int nf2 = 0; nf2 < 4; nf2++)
                    ldmx4(bfl[nf2][0], bfl[nf2][1], bfl[nf2][2], bfl[nf2][3],
                          b_lo + (uint32_t)(nf2 * 2048) + bo);
                #pragma unroll
                for (int mf = 0; mf < 4; mf++)
                    #pragma unroll
                    for (int nf = 0; nf < 8; nf++)
                        mma16816(acc[mf][nf], afh[mf],
                                 bfl[nf >> 1][nf & 1], bfl[nf >> 1][(nf & 1) + 2]);
            }
            /* term 3: Alo * Bhi */
            {
                uint32_t afl[4][4];
                #pragma unroll
                for (int mf = 0; mf < 4; mf++)
                    ldmx4(afl[mf][0], afl[mf][1], afl[mf][2], afl[mf][3],
                          a_lo + (uint32_t)(mf * 2048) + ao);
                #pragma unroll
                for (int mf = 0; mf < 4; mf++)
                    #pragma unroll
                    for (int nf = 0; nf < 8; nf++)
                        mma16816(acc[mf][nf], afl[mf],
                                 bfh[nf >> 1][nf & 1], bfh[nf >> 1][(nf & 1) + 2]);
            }
        }
        __syncthreads();
    }

    int r0 = lane >> 2, cb = (lane & 3) * 2;
    if (PARTIAL) {
        float* Cp = C + (size_t)blockIdx.z * M * N;
        #pragma unroll
        for (int mf = 0; mf < 4; mf++)
            #pragma unroll
            for (int nf = 0; nf < 8; nf++) {
                int n0 = bn + wn * 64 + nf * 8 + cb;
                #pragma unroll
                for (int half = 0; half < 2; half++) {
                    int m0 = bm + wm * 64 + mf * 16 + r0 + half * 8;
                    *(float2*)(Cp + (size_t)m0 * N + n0) =
                        make_float2(acc[mf][nf][half * 2], acc[mf][nf][half * 2 + 1]);
                }
            }
        return;
    }
    #pragma unroll
    for (int mf = 0; mf < 4; mf++) {
        #pragma unroll
        for (int nf = 0; nf < 8; nf++) {
            int n0 = bn + wn * 64 + nf * 8 + cb;
            float bz0 = bias ? bias[n0]     : 0.f;
            float bz1 = bias ? bias[n0 + 1] : 0.f;
            #pragma unroll
            for (int half = 0; half < 2; half++) {
                int m0 = bm + wm * 64 + mf * 16 + r0 + half * 8;
                float v0 = acc[mf][nf][half * 2]     + bz0;
                float v1 = acc[mf][nf][half * 2 + 1] + bz1;
                if (ROPE) {
                    if (n0 < 2*DIM) {
                        int pos = m0 & (NTOK - 1);
                        int d   = n0 & (HD - 1);
                        const float* e = remb + pos * (2*HD);
                        float2 sn = *(const float2*)(e + d);
                        float2 cs = *(const float2*)(e + HD + d);
                        float t0 = v0 * cs.x - v1 * sn.x;
                        float t1 = v1 * cs.y + v0 * sn.y;
                        v0 = t0; v1 = t1;
                    }
                }
                size_t idx = (size_t)m0 * N + n0;
                if (res) { v0 += res[idx]; v1 += res[idx + 1]; }
                *(float2*)(C + idx) = make_float2(v0, v1);
            }
        }
    }
}

/* ------------------------------------------------------------------ */
/* reduce3: h += bias + p0 + p1 + p2                                   */
/* ------------------------------------------------------------------ */
__global__ void reduce3(float* __restrict__ h, const float* __restrict__ part,
                        const float* __restrict__ bias) {
    int i = blockIdx.x * blockDim.x + threadIdx.x;
    if (i >= TOKENS*DIM/4) return;
    float4 a  = ((const float4*)h)[i];
    float4 p0 = ((const float4*)part)[i];
    float4 p1 = ((const float4*)(part + TOKENS*DIM))[i];
    float4 p2 = ((const float4*)(part + 2*TOKENS*DIM))[i];
    float4 bz = *(const float4*)(bias + (i*4) % DIM);
    a.x += bz.x + ((p0.x + p1.x) + p2.x);
    a.y += bz.y + ((p0.y + p1.y) + p2.y);
    a.z += bz.z + ((p0.z + p1.z) + p2.z);
    a.w += bz.w + ((p0.w + p1.w) + p2.w);
    ((float4*)h)[i] = a;
}

/* ------------------------------------------------------------------ */
/* Single fused fp32 -> (hi, lo) split+pack for ALL weights            */
/* ------------------------------------------------------------------ */
struct CvtArgs {
    const float* src[7];
    __half* hi[7];
    __half* lo[7];
    int lr[7];
    int ltot[7];
    int off[7];
    int cum[8];
};
__device__ __forceinline__ void split2(float a, float b, __half2& h, __half2& l) {
    __half ha = __float2half_rn(a), hb = __float2half_rn(b);
    __half la = __float2half_rn(a - __half2float(ha));
    __half lb = __float2half_rn(b - __half2float(hb));
    h = __halves2half2(ha, hb);
    l = __halves2half2(la, lb);
}
__global__ void cvt_all(CvtArgs a, int total4) {
    int i4 = blockIdx.x * blockDim.x + threadIdx.x;
    if (i4 >= total4) return;
    int s = 0;
    #pragma unroll
    for (int j = 1; j < 7; j++) s += (i4 >= a.cum[j]);
    int i = (i4 - a.cum[s]) * 4;
    int l = i / a.lr[s];
    int rem = i - l * a.lr[s];
    size_t d = (size_t)l * a.ltot[s] + a.off[s] + rem;
    float4 v = *(const float4*)(a.src[s] + i);
    __half2 h0, l0, h1, l1;
    split2(v.x, v.y, h0, l0);
    split2(v.z, v.w, h1, l1);
    ((__half2*)(a.hi[s] + d))[0] = h0; ((__half2*)(a.hi[s] + d))[1] = h1;
    ((__half2*)(a.lo[s] + d))[0] = l0; ((__half2*)(a.lo[s] + d))[1] = l1;
}

/* ------------------------------------------------------------------ */
/* add_pos + bias packing fused                                        */
/* ------------------------------------------------------------------ */
__global__ void add_pos_prep(const float* __restrict__ x,
                             const float* __restrict__ pos,
                             float* __restrict__ h,
                             const float* __restrict__ bq,
                             const float* __restrict__ bv,
                             float* __restrict__ bqkv,
                             const float* __restrict__ bg,
                             const float* __restrict__ bx,
                             float* __restrict__ b1) {
    int idx = blockIdx.x * blockDim.x + threadIdx.x;
    if (idx < TOKENS*DIM) h[idx] = x[idx] + pos[idx % (NTOK*DIM)];
    if (idx < DEPTH*QS) {
        int l = idx / QS, c = idx % QS;
        bqkv[idx] = c < DIM ? bq[l*DIM + c]
                  : (c < 2*DIM ? 0.f : bv[l*DIM + c - 2*DIM]);
    }
    if (idx < DEPTH*GUS) {
        int l = idx / GUS, c = idx % GUS;
        b1[idx] = c < HIDDEN ? bg[l*HIDDEN + c] : bx[l*HIDDEN + c - HIDDEN];
    }
}

/* ------------------------------------------------------------------ */
/* Block reduction (256 threads)                                       */
/* ------------------------------------------------------------------ */
__device__ __forceinline__ float2 block_reduce_2(float s, float s2) {
    __shared__ float red[16];
    #pragma unroll
    for (int o = 16; o > 0; o >>= 1) {
        s  += __shfl_down_sync(0xffffffffu, s,  o);
        s2 += __shfl_down_sync(0xffffffffu, s2, o);
    }
    int w = threadIdx.x >> 5, l = threadIdx.x & 31;
    if (l == 0) { red[w] = s; red[8 + w] = s2; }
    __syncthreads();
    if (threadIdx.x < 32) {
        s  = (l < 8) ? red[l]     : 0.f;
        s2 = (l < 8) ? red[8 + l] : 0.f;
        #pragma unroll
        for (int o = 4; o > 0; o >>= 1) {
            s  += __shfl_down_sync(0xffffffffu, s,  o);
            s2 += __shfl_down_sync(0xffffffffu, s2, o);
        }
        if (l == 0) { red[0] = s; red[1] = s2; }
    }
    __syncthreads();
    return make_float2(red[0], red[1]);
}

__device__ __forceinline__ uint32_t pack_h2(float a, float b) {
    __half2 h = __floats2half2_rn(a, b);
    return *(uint32_t*)&h;
}

/* ------------------------------------------------------------------ */
/* LayerNorm over DIM (vectorized)                                     */
/* ------------------------------------------------------------------ */
__global__ void __launch_bounds__(256) ln_kernel(
    const float* __restrict__ x, const float* __restrict__ w,
    const float* __restrict__ b, __half* __restrict__ ohi,
    __half* __restrict__ olo) {
    int t = blockIdx.x;
    int c4 = threadIdx.x;
    float4 v = make_float4(0.f, 0.f, 0.f, 0.f);
    if (c4 < DIM/4) v = ((const float4*)(x + (size_t)t * DIM))[c4];
    float s  = v.x + v.y + v.z + v.w;
    float s2 = v.x*v.x + v.y*v.y + v.z*v.z + v.w*v.w;
    float2 r = block_reduce_2(s, s2);
    float mean = r.x / DIM;
    float var  = r.y / DIM - mean * mean;
    float inv  = rsqrtf(var + EPSF);
    if (c4 < DIM/4) {
        float4 wv = ((const float4*)w)[c4];
        float4 bv = ((const float4*)b)[c4];
        float y0 = (v.x - mean) * inv * wv.x + bv.x;
        float y1 = (v.y - mean) * inv * wv.y + bv.y;
        float y2 = (v.z - mean) * inv * wv.z + bv.z;
        float y3 = (v.w - mean) * inv * wv.w + bv.w;
        __half h0 = __float2half_rn(y0), h1 = __float2half_rn(y1);
        __half h2 = __float2half_rn(y2), h3 = __float2half_rn(y3);
        uint2 hi = make_uint2(pack_h2(y0, y1), pack_h2(y2, y3));
        uint2 lo = make_uint2(pack_h2(y0 - __half2float(h0), y1 - __half2float(h1)),
                              pack_h2(y2 - __half2float(h2), y3 - __half2float(h3)));
        ((uint2*)ohi)[(size_t)t * (DIM/4) + c4] = hi;
        ((uint2*)olo)[(size_t)t * (DIM/4) + c4] = lo;
    }
}

/* ------------------------------------------------------------------ */
/* silu(g)*u then LN over HIDDEN (register-resident)                   */
/* ------------------------------------------------------------------ */
__global__ void __launch_bounds__(256) mlp_act_ln_kernel(
    const float* __restrict__ gu,
    const float* __restrict__ w, const float* __restrict__ b,
    __half* __restrict__ ohi, __half* __restrict__ olo) {
    int t = blockIdx.x;
    const float* gr = gu + (size_t)t * GUS;
    const float* ur = gr + HIDDEN;
    float a[8];
    float s = 0.f, s2 = 0.f;
    #pragma unroll
    for (int j = 0; j < 2; j++) {
        int c4 = threadIdx.x + j * 256;
        float4 gv = ((const float4*)gr)[c4];
        float4 uv = ((const float4*)ur)[c4];
        float* aj = a + j * 4;
        aj[0] = gv.x / (1.f + __expf(-gv.x)) * uv.x;
        aj[1] = gv.y / (1.f + __expf(-gv.y)) * uv.y;
        aj[2] = gv.z / (1.f + __expf(-gv.z)) * uv.z;
        aj[3] = gv.w / (1.f + __expf(-gv.w)) * uv.w;
        s  += aj[0] + aj[1] + aj[2] + aj[3];
        s2 += aj[0]*aj[0] + aj[1]*aj[1] + aj[2]*aj[2] + aj[3]*aj[3];
    }
    float2 r = block_reduce_2(s, s2);
    float mean = r.x / HIDDEN;
    float var  = r.y / HIDDEN - mean * mean;
    float inv  = rsqrtf(var + EPSF);
    #pragma unroll
    for (int j = 0; j < 2; j++) {
        int c4 = threadIdx.x + j * 256;
        float4 wv = ((const float4*)w)[c4];
        float4 bv = ((const float4*)b)[c4];
        float* aj = a + j * 4;
        float y0 = (aj[0] - mean) * inv * wv.x + bv.x;
        float y1 = (aj[1] - mean) * inv * wv.y + bv.y;
        float y2 = (aj[2] - mean) * inv * wv.z + bv.z;
        float y3 = (aj[3] - mean) * inv * wv.w + bv.w;
        __half h0 = __float2half_rn(y0), h1 = __float2half_rn(y1);
        __half h2 = __float2half_rn(y2), h3 = __float2half_rn(y3);
        uint2 hi = make_uint2(pack_h2(y0, y1), pack_h2(y2, y3));
        uint2 lo = make_uint2(pack_h2(y0 - __half2float(h0), y1 - __half2float(h1)),
                              pack_h2(y2 - __half2float(h2), y3 - __half2float(h3)));
        ((uint2*)ohi)[(size_t)t * (HIDDEN/4) + c4] = hi;
        ((uint2*)olo)[(size_t)t * (HIDDEN/4) + c4] = lo;
    }
}

/* ------------------------------------------------------------------ */
/* Attention                                                           */
/* ------------------------------------------------------------------ */
#define KVT 128
__global__ void __launch_bounds__(256) attn_kernel(
    const float* __restrict__ qkv, __half* __restrict__ ohi,
    __half* __restrict__ olo) {
    extern __shared__ float sm[];
    float* Ks = sm;
    float* Vs = sm + KVT * HD;
    int blk = blockIdx.x;
    int half_blk = blk & 1;
    int bh = blk >> 1;
    int b  = bh / HEADS, h = bh % HEADS;
    size_t base_q = (size_t)(b * NTOK) * QS + h * HD;
    int tid = threadIdx.x, lane = tid & 31, wid = tid >> 5;
    int row_local = wid * 16 + (lane & 15);
    int part = lane >> 4;
    int i = half_blk * 128 + row_local;

    const float scale = 0.125f;
    float qreg[32];
    {
        const float* qp = qkv + base_q + (size_t)i * QS + part * 32;
        #pragma unroll
        for (int d = 0; d < 32; d++) qreg[d] = qp[d] * scale;
    }

    float mrun = -1e30f, lrun = 0.f;
    float accv[32];
    #pragma unroll
    for (int d = 0; d < 32; d++) accv[d] = 0.f;

    for (int tkv = 0; tkv < NTOK / KVT; tkv++) {
        for (int idx = tid; idx < KVT * HD; idx += 256) {
            int row = idx >> 6, col = idx & 63;
            size_t src = base_q + (size_t)(tkv * KVT + row) * QS + col;
            Ks[idx] = qkv[src + DIM];
            Vs[idx] = qkv[src + 2*DIM];
        }
        __syncthreads();

        for (int j = 0; j < KVT; j++) {
            const float* kr = Ks + j * HD + part * 32;
            float s = 0.f;
            #pragma unroll
            for (int d = 0; d < 32; d++) s += qreg[d] * kr[d];
            s += __shfl_xor_sync(0xffffffffu, s, 16);
            float mnew = fmaxf(mrun, s);
            float cc = __expf(mrun - mnew);
            float p  = __expf(s - mnew);
            lrun = lrun * cc + p;
            const float* vr = Vs + j * HD + part * 32;
            #pragma unroll
            for (int d = 0; d < 32; d++) accv[d] = accv[d] * cc + p * vr[d];
            mrun = mnew;
        }
        __syncthreads();
    }

    float inv = 1.f / lrun;
    size_t ob = (size_t)(b * NTOK + i) * DIM + h * HD + part * 32;
    #pragma unroll
    for (int d = 0; d < 32; d++) {
        float v0 = accv[d] * inv;
        __half hh = __float2half_rn(v0);
        ohi[ob + d] = hh;
        olo[ob + d] = __float2half_rn(v0 - __half2float(hh));
    }
}

/* ------------------------------------------------------------------ */
/* Launch                                                              */
/* ------------------------------------------------------------------ */
extern "C" void kernel_launch(void* const* d_in, const int* in_sizes, int n_in,
                              void* d_out, int out_size) {
    const float* x      = (const float*)d_in[0];
    const float* pos    = (const float*)d_in[1];
    const float* rope   = (const float*)d_in[2];
    const float* ln1_w  = (const float*)d_in[3];
    const float* ln1_b  = (const float*)d_in[4];
    const float* wq     = (const float*)d_in[5];
    const float* bq     = (const float*)d_in[6];
    const float* wk     = (const float*)d_in[7];
    const float* wv     = (const float*)d_in[8];
    const float* bv     = (const float*)d_in[9];
    const float* wo     = (const float*)d_in[10];
    const float* bo     = (const float*)d_in[11];
    const float* ln2_w  = (const float*)d_in[12];
    const float* ln2_b  = (const float*)d_in[13];
    const float* w1g    = (const float*)d_in[14];
    const float* b1g    = (const float*)d_in[15];
    const float* w1x    = (const float*)d_in[16];
    const float* b1x    = (const float*)d_in[17];
    const float* lnm_w  = (const float*)d_in[18];
    const float* lnm_b  = (const float*)d_in[19];
    const float* w2     = (const float*)d_in[20];
    const float* b2     = (const float*)d_in[21];
    float* h = (float*)d_out;

    float *qkv, *gu, *bqkv, *b1, *part;
    __half *yhh, *yhl, *ohh, *ohl, *mhh, *mhl;
    __half *wqkvh, *wqkvl, *woh, *wol, *w1h, *w1l, *w2h, *w2l;
    cudaGetSymbolAddress((void**)&qkv,   g_qkv);
    cudaGetSymbolAddress((void**)&gu,    g_gu);
    cudaGetSymbolAddress((void**)&part,  g_part);
    cudaGetSymbolAddress((void**)&bqkv,  g_bqkv);
    cudaGetSymbolAddress((void**)&b1,    g_b1);
    cudaGetSymbolAddress((void**)&yhh,   g_yh_hi);
    cudaGetSymbolAddress((void**)&yhl,   g_yh_lo);
    cudaGetSymbolAddress((void**)&ohh,   g_oh_hi);
    cudaGetSymbolAddress((void**)&ohl,   g_oh_lo);
    cudaGetSymbolAddress((void**)&mhh,   g_mh_hi);
    cudaGetSymbolAddress((void**)&mhl,   g_mh_lo);
    cudaGetSymbolAddress((void**)&wqkvh, g_wqkv_hi);
    cudaGetSymbolAddress((void**)&wqkvl, g_wqkv_lo);
    cudaGetSymbolAddress((void**)&woh,   g_wo_hi);
    cudaGetSymbolAddress((void**)&wol,   g_wo_lo);
    cudaGetSymbolAddress((void**)&w1h,   g_w1_hi);
    cudaGetSymbolAddress((void**)&w1l,   g_w1_lo);
    cudaGetSymbolAddress((void**)&w2h,   g_w2_hi);
    cudaGetSymbolAddress((void**)&w2l,   g_w2_lo);

    cudaFuncSetAttribute((const void*)gemm_mma<true,false>,
                         cudaFuncAttributeMaxDynamicSharedMemorySize, GEMM_SMEM);
    cudaFuncSetAttribute((const void*)gemm_mma<false,false>,
                         cudaFuncAttributeMaxDynamicSharedMemorySize, GEMM_SMEM);
    cudaFuncSetAttribute((const void*)gemm_mma<false,true>,
                         cudaFuncAttributeMaxDynamicSharedMemorySize, GEMM_SMEM);
    cudaFuncSetAttribute((const void*)attn_kernel,
                         cudaFuncAttributeMaxDynamicSharedMemorySize,
                         2 * KVT * HD * (int)sizeof(float));

    /* ---- [1] fused weight split + pack ---- */
    {
        const int nD = DIM*DIM, nH = HIDDEN*DIM;
        CvtArgs a;
        const float* srcs[7] = { wq, wk, wv, wo, w1g, w1x, w2 };
        __half* his[7] = { wqkvh, wqkvh, wqkvh, woh, w1h, w1h, w2h };
        __half* los[7] = { wqkvl, wqkvl, wqkvl, wol, w1l, w1l, w2l };
        int lrs[7]   = { nD, nD, nD, nD, nH, nH, nH };
        int ltots[7] = { QS*DIM, QS*DIM, QS*DIM, nD, GUS*DIM, GUS*DIM, nH };
        int offs[7]  = { 0, nD, 2*nD, 0, 0, nH, 0 };
        int cum = 0;
        for (int s = 0; s < 7; s++) {
            a.src[s] = srcs[s]; a.hi[s] = his[s]; a.lo[s] = los[s];
            a.lr[s] = lrs[s]; a.ltot[s] = ltots[s]; a.off[s] = offs[s];
            a.cum[s] = cum;
            cum += DEPTH * lrs[s] / 4;
        }
        a.cum[7] = cum;
        cvt_all<<<(cum + 255)/256, 256>>>(a, cum);
    }
    /* ---- [2] pos-embed add + bias packing ---- */
    add_pos_prep<<<(TOKENS*DIM + 255)/256, 256>>>(x, pos, h, bq, bv, bqkv,
                                                  b1g, b1x, b1);

    dim3 gQKV(QS/256,  TOKENS/128);      /* (9, 32)    */
    dim3 gMLP(GUS/256, TOKENS/128);      /* (16, 32)   */
    dim3 gSK (DIM/256, TOKENS/128, 3);   /* (3, 32, 3) */
    const int RED = (TOKENS*DIM/4 + 255)/256;

    for (int l = 0; l < DEPTH; l++) {
        size_t oqkv = (size_t)l * QS * DIM;
        size_t owo  = (size_t)l * DIM * DIM;
        size_t ow1  = (size_t)l * GUS * DIM;
        size_t ow2  = (size_t)l * DIM * HIDDEN;

        /* ---- attention ---- */
        ln_kernel<<<TOKENS, 256>>>(h, ln1_w + l*DIM, ln1_b + l*DIM, yhh, yhl);
        gemm_mma<true,false><<<gQKV, 256, GEMM_SMEM>>>(
            yhh, yhl, wqkvh + oqkv, wqkvl + oqkv,
            bqkv + l*QS, nullptr, qkv, rope, TOKENS, QS, DIM);
        attn_kernel<<<BATCH*HEADS*2, 256, 2*KVT*HD*sizeof(float)>>>(qkv, ohh, ohl);
        gemm_mma<false,true><<<gSK, 256, GEMM_SMEM>>>(
            ohh, ohl, woh + owo, wol + owo,
            nullptr, nullptr, part, nullptr, TOKENS, DIM, DIM);
        reduce3<<<RED, 256>>>(h, part, bo + l*DIM);

        /* ---- SwiGLU MLP ---- */
        ln_kernel<<<TOKENS, 256>>>(h, ln2_w + l*DIM, ln2_b + l*DIM, yhh, yhl);
        gemm_mma<false,false><<<gMLP, 256, GEMM_SMEM>>>(
            yhh, yhl, w1h + ow1, w1l + ow1,
            b1 + l*GUS, nullptr, gu, nullptr, TOKENS, GUS, DIM);
        mlp_act_ln_kernel<<<TOKENS, 256>>>(gu, lnm_w + l*HIDDEN, lnm_b + l*HIDDEN, mhh, mhl);
        gemm_mma<false,true><<<gSK, 256, GEMM_SMEM>>>(
            mhh, mhl, w2h + ow2, w2l + ow2,
            nullptr, nullptr, part, nullptr, TOKENS, DIM, HIDDEN);
        reduce3<<<RED, 256>>>(h, part, b2 + l*DIM);
    }
}

// round 10
// speedup vs baseline: 1.1645x; 1.0040x over previous
#include <cuda_runtime.h>
#include <cuda_fp16.h>
#include <math.h>
#include <stdint.h>

#define DEPTH   12
#define BATCH   16
#define NTOK    256
#define TOKENS  (BATCH*NTOK)     /* 4096 */
#define DIM     768
#define HEADS   12
#define HD      64
#define HIDDEN  2048
#define EPSF    1e-5f
#define QS      2304             /* packed qkv row stride */
#define GUS     4096             /* packed g|u row stride */

/* ------------------------------------------------------------------ */
/* Scratch buffers                                                     */
/* ------------------------------------------------------------------ */
__device__ float  g_qkv[TOKENS*QS];
__device__ float  g_gu[TOKENS*GUS];
__device__ float  g_part[3*TOKENS*DIM];
__device__ __half g_yh_hi[TOKENS*DIM];
__device__ __half g_yh_lo[TOKENS*DIM];
__device__ __half g_oh_hi[TOKENS*DIM];
__device__ __half g_oh_lo[TOKENS*DIM];
__device__ __half g_mh_hi[TOKENS*HIDDEN];
__device__ __half g_mh_lo[TOKENS*HIDDEN];

/* packed split weights */
__device__ __half g_wqkv_hi[DEPTH*QS*DIM];
__device__ __half g_wqkv_lo[DEPTH*QS*DIM];
__device__ __half g_wo_hi[DEPTH*DIM*DIM];
__device__ __half g_wo_lo[DEPTH*DIM*DIM];
__device__ __half g_w1_hi[DEPTH*GUS*DIM];
__device__ __half g_w1_lo[DEPTH*GUS*DIM];
__device__ __half g_w2_hi[DEPTH*DIM*HIDDEN];
__device__ __half g_w2_lo[DEPTH*DIM*HIDDEN];
__device__ float  g_bqkv[DEPTH*QS];
__device__ float  g_b1[DEPTH*GUS];

/* ------------------------------------------------------------------ */
/* PTX helpers                                                         */
/* ------------------------------------------------------------------ */
__device__ __forceinline__ uint32_t smem_u32(const void* p) {
    uint32_t a;
    asm("{ .reg .u64 t; cvta.to.shared.u64 t, %1; cvt.u32.u64 %0, t; }"
        : "=r"(a) : "l"(p));
    return a;
}
__device__ __forceinline__ void cp16(uint32_t dst, const void* src) {
    asm volatile("cp.async.cg.shared.global [%0], [%1], 16;"
                 :: "r"(dst), "l"(src) : "memory");
}
__device__ __forceinline__ void cp_commit() {
    asm volatile("cp.async.commit_group;" ::: "memory");
}
template<int NWAIT>
__device__ __forceinline__ void cp_wait() {
    asm volatile("cp.async.wait_group %0;" :: "n"(NWAIT) : "memory");
}
/* ldmatrix x4 with compile-time immediate offset: [reg + IMM] */
template<int IMM>
__device__ __forceinline__ void ldmx4i(uint32_t& r0, uint32_t& r1,
                                       uint32_t& r2, uint32_t& r3, uint32_t a) {
    asm volatile("ldmatrix.sync.aligned.m8n8.x4.shared.b16 {%0,%1,%2,%3}, [%4+%5];"
                 : "=r"(r0), "=r"(r1), "=r"(r2), "=r"(r3) : "r"(a), "n"(IMM));
}
#define LDM4(f, base) do {                                        \
    ldmx4i<0>   ((f)[0][0], (f)[0][1], (f)[0][2], (f)[0][3], base); \
    ldmx4i<2048>((f)[1][0], (f)[1][1], (f)[1][2], (f)[1][3], base); \
    ldmx4i<4096>((f)[2][0], (f)[2][1], (f)[2][2], (f)[2][3], base); \
    ldmx4i<6144>((f)[3][0], (f)[3][1], (f)[3][2], (f)[3][3], base); \
} while (0)

__device__ __forceinline__ void mma16816(float* c, const uint32_t* a,
                                         uint32_t b0, uint32_t b1) {
    asm("mma.sync.aligned.m16n8k16.row.col.f32.f16.f16.f32 "
        "{%0,%1,%2,%3}, {%4,%5,%6,%7}, {%8,%9}, {%0,%1,%2,%3};"
        : "+f"(c[0]), "+f"(c[1]), "+f"(c[2]), "+f"(c[3])
        : "r"(a[0]), "r"(a[1]), "r"(a[2]), "r"(a[3]), "r"(b0), "r"(b1));
}

/* ------------------------------------------------------------------ */
/* Split-fp16 HMMA GEMM (NT): C = Ahi*Bhi + Ahi*Blo + Alo*Bhi          */
/* CTA tile 128x256, 8 warps of 64x64 (2x4), BK=64, double-buffered.   */
/* Mainloop: immediate-offset LDSM + term-sequential fragments.        */
/* ------------------------------------------------------------------ */
#define PA 16384
#define PB 32768
#define BUFSZ (2*PA + 2*PB)            /* 98304 */
#define GEMM_SMEM (2*BUFSZ)            /* 196608 */

template<bool ROPE, bool PARTIAL>
__global__ void __launch_bounds__(256, 1) gemm_mma(
    const __half* __restrict__ Ahi, const __half* __restrict__ Alo,
    const __half* __restrict__ Bhi, const __half* __restrict__ Blo,
    const float* __restrict__ bias, const float* __restrict__ res,
    float* __restrict__ C, const float* __restrict__ remb,
    int M, int N, int K) {
    extern __shared__ __align__(128) char smem[];
    uint32_t sb = smem_u32(smem);
    int tid = threadIdx.x, wid = tid >> 5, lane = tid & 31;
    int wm = wid >> 2, wn = wid & 3;
    int bm = blockIdx.y * 128, bn = blockIdx.x * 256;

    int l15 = lane & 15, kg = lane >> 4;
    uint32_t arow = (uint32_t)(wm * 64 + l15);
    uint32_t brow = (uint32_t)(wn * 64 + l15);
    int aswz = (int)(arow & 7), bswz = (int)(brow & 7);

    uint32_t aoff[4], boff[4];
    #pragma unroll
    for (int ks = 0; ks < 4; ks++) {
        int g = ks * 2 + kg;
        aoff[ks] = (uint32_t)((g ^ aswz) * 16);
        boff[ks] = (uint32_t)((g ^ bswz) * 16);
    }
    /* buffer-0 plane bases (buffer 1 = +BUFSZ) */
    uint32_t aHi0 = sb             + arow * 128u;
    uint32_t aLo0 = sb + PA        + arow * 128u;
    uint32_t bHi0 = sb + 2*PA      + brow * 128u;
    uint32_t bLo0 = sb + 2*PA + PB + brow * 128u;

    float acc[4][8][4];
    #pragma unroll
    for (int i = 0; i < 4; i++)
        #pragma unroll
        for (int j = 0; j < 8; j++)
            #pragma unroll
            for (int e = 0; e < 4; e++) acc[i][j][e] = 0.f;

    int nch = K >> 6;
    int c0 = 0, c1 = nch;
    if (PARTIAL) {
        int z = blockIdx.z;
        c0 = (z * nch) / 3;
        c1 = ((z + 1) * nch) / 3;
    }

    auto load_chunk = [&](uint32_t dst, int ko) {
        #pragma unroll
        for (int j = 0; j < 4; j++) {
            int id = tid + j * 256;
            int row = id >> 3, g = id & 7;
            uint32_t off = (uint32_t)row * 128u + (uint32_t)((g ^ (row & 7)) * 16);
            size_t so = (size_t)(bm + row) * K + ko + g * 8;
            cp16(dst + off,      Ahi + so);
            cp16(dst + PA + off, Alo + so);
        }
        #pragma unroll
        for (int j = 0; j < 8; j++) {
            int id = tid + j * 256;
            int row = id >> 3, g = id & 7;
            uint32_t off = (uint32_t)row * 128u + (uint32_t)((g ^ (row & 7)) * 16);
            size_t so = (size_t)(bn + row) * K + ko + g * 8;
            cp16(dst + 2*PA + off,      Bhi + so);
            cp16(dst + 2*PA + PB + off, Blo + so);
        }
    };

    load_chunk(sb, c0 * 64);
    cp_commit();

    for (int c = c0; c < c1; c++) {
        if (c + 1 < c1) {
            load_chunk(sb + (uint32_t)(((c - c0 + 1) & 1) * BUFSZ), (c + 1) * 64);
            cp_commit();
            cp_wait<1>();
        } else {
            cp_wait<0>();
        }
        __syncthreads();

        uint32_t bofs = (uint32_t)(((c - c0) & 1) ? BUFSZ : 0);
        uint32_t a_hi = aHi0 + bofs, a_lo = aLo0 + bofs;
        uint32_t b_hi = bHi0 + bofs, b_lo = bLo0 + bofs;

        #pragma unroll
        for (int ks = 0; ks < 4; ks++) {
            /* term 1: Ahi * Bhi */
            uint32_t afh[4][4], bfh[4][4];
            LDM4(afh, a_hi + aoff[ks]);
            LDM4(bfh, b_hi + boff[ks]);
            #pragma unroll
            for (int mf = 0; mf < 4; mf++)
                #pragma unroll
                for (int nf = 0; nf < 8; nf++)
                    mma16816(acc[mf][nf], afh[mf],
                             bfh[nf >> 1][nf & 1], bfh[nf >> 1][(nf & 1) + 2]);
            /* term 2: Ahi * Blo */
            {
                uint32_t bfl[4][4];
                LDM4(bfl, b_lo + boff[ks]);
                #pragma unroll
                for (int mf = 0; mf < 4; mf++)
                    #pragma unroll
                    for (int nf = 0; nf < 8; nf++)
                        mma16816(acc[mf][nf], afh[mf],
                                 bfl[nf >> 1][nf & 1], bfl[nf >> 1][(nf & 1) + 2]);
            }
            /* term 3: Alo * Bhi */
            {
                uint32_t afl[4][4];
                LDM4(afl, a_lo + aoff[ks]);
                #pragma unroll
                for (int mf = 0; mf < 4; mf++)
                    #pragma unroll
                    for (int nf = 0; nf < 8; nf++)
                        mma16816(acc[mf][nf], afl[mf],
                                 bfh[nf >> 1][nf & 1], bfh[nf >> 1][(nf & 1) + 2]);
            }
        }
        __syncthreads();
    }

    int r0 = lane >> 2, cb = (lane & 3) * 2;
    if (PARTIAL) {
        float* Cp = C + (size_t)blockIdx.z * M * N;
        #pragma unroll
        for (int mf = 0; mf < 4; mf++)
            #pragma unroll
            for (int nf = 0; nf < 8; nf++) {
                int n0 = bn + wn * 64 + nf * 8 + cb;
                #pragma unroll
                for (int half = 0; half < 2; half++) {
                    int m0 = bm + wm * 64 + mf * 16 + r0 + half * 8;
                    *(float2*)(Cp + (size_t)m0 * N + n0) =
                        make_float2(acc[mf][nf][half * 2], acc[mf][nf][half * 2 + 1]);
                }
            }
        return;
    }
    #pragma unroll
    for (int mf = 0; mf < 4; mf++) {
        #pragma unroll
        for (int nf = 0; nf < 8; nf++) {
            int n0 = bn + wn * 64 + nf * 8 + cb;
            float bz0 = bias ? bias[n0]     : 0.f;
            float bz1 = bias ? bias[n0 + 1] : 0.f;
            #pragma unroll
            for (int half = 0; half < 2; half++) {
                int m0 = bm + wm * 64 + mf * 16 + r0 + half * 8;
                float v0 = acc[mf][nf][half * 2]     + bz0;
                float v1 = acc[mf][nf][half * 2 + 1] + bz1;
                if (ROPE) {
                    if (n0 < 2*DIM) {
                        int pos = m0 & (NTOK - 1);
                        int d   = n0 & (HD - 1);
                        const float* e = remb + pos * (2*HD);
                        float2 sn = *(const float2*)(e + d);
                        float2 cs = *(const float2*)(e + HD + d);
                        float t0 = v0 * cs.x - v1 * sn.x;
                        float t1 = v1 * cs.y + v0 * sn.y;
                        v0 = t0; v1 = t1;
                    }
                }
                size_t idx = (size_t)m0 * N + n0;
                if (res) { v0 += res[idx]; v1 += res[idx + 1]; }
                *(float2*)(C + idx) = make_float2(v0, v1);
            }
        }
    }
}

/* ------------------------------------------------------------------ */
/* reduce3: h += bias + p0 + p1 + p2                                   */
/* ------------------------------------------------------------------ */
__global__ void reduce3(float* __restrict__ h, const float* __restrict__ part,
                        const float* __restrict__ bias) {
    int i = blockIdx.x * blockDim.x + threadIdx.x;
    if (i >= TOKENS*DIM/4) return;
    float4 a  = ((const float4*)h)[i];
    float4 p0 = ((const float4*)part)[i];
    float4 p1 = ((const float4*)(part + TOKENS*DIM))[i];
    float4 p2 = ((const float4*)(part + 2*TOKENS*DIM))[i];
    float4 bz = *(const float4*)(bias + (i*4) % DIM);
    a.x += bz.x + ((p0.x + p1.x) + p2.x);
    a.y += bz.y + ((p0.y + p1.y) + p2.y);
    a.z += bz.z + ((p0.z + p1.z) + p2.z);
    a.w += bz.w + ((p0.w + p1.w) + p2.w);
    ((float4*)h)[i] = a;
}

/* ------------------------------------------------------------------ */
/* Single fused fp32 -> (hi, lo) split+pack for ALL weights            */
/* ------------------------------------------------------------------ */
struct CvtArgs {
    const float* src[7];
    __half* hi[7];
    __half* lo[7];
    int lr[7];
    int ltot[7];
    int off[7];
    int cum[8];
};
__device__ __forceinline__ void split2(float a, float b, __half2& h, __half2& l) {
    __half ha = __float2half_rn(a), hb = __float2half_rn(b);
    __half la = __float2half_rn(a - __half2float(ha));
    __half lb = __float2half_rn(b - __half2float(hb));
    h = __halves2half2(ha, hb);
    l = __halves2half2(la, lb);
}
__global__ void cvt_all(CvtArgs a, int total4) {
    int i4 = blockIdx.x * blockDim.x + threadIdx.x;
    if (i4 >= total4) return;
    int s = 0;
    #pragma unroll
    for (int j = 1; j < 7; j++) s += (i4 >= a.cum[j]);
    int i = (i4 - a.cum[s]) * 4;
    int l = i / a.lr[s];
    int rem = i - l * a.lr[s];
    size_t d = (size_t)l * a.ltot[s] + a.off[s] + rem;
    float4 v = *(const float4*)(a.src[s] + i);
    __half2 h0, l0, h1, l1;
    split2(v.x, v.y, h0, l0);
    split2(v.z, v.w, h1, l1);
    ((__half2*)(a.hi[s] + d))[0] = h0; ((__half2*)(a.hi[s] + d))[1] = h1;
    ((__half2*)(a.lo[s] + d))[0] = l0; ((__half2*)(a.lo[s] + d))[1] = l1;
}

/* ------------------------------------------------------------------ */
/* add_pos + bias packing fused                                        */
/* ------------------------------------------------------------------ */
__global__ void add_pos_prep(const float* __restrict__ x,
                             const float* __restrict__ pos,
                             float* __restrict__ h,
                             const float* __restrict__ bq,
                             const float* __restrict__ bv,
                             float* __restrict__ bqkv,
                             const float* __restrict__ bg,
                             const float* __restrict__ bx,
                             float* __restrict__ b1) {
    int idx = blockIdx.x * blockDim.x + threadIdx.x;
    if (idx < TOKENS*DIM) h[idx] = x[idx] + pos[idx % (NTOK*DIM)];
    if (idx < DEPTH*QS) {
        int l = idx / QS, c = idx % QS;
        bqkv[idx] = c < DIM ? bq[l*DIM + c]
                  : (c < 2*DIM ? 0.f : bv[l*DIM + c - 2*DIM]);
    }
    if (idx < DEPTH*GUS) {
        int l = idx / GUS, c = idx % GUS;
        b1[idx] = c < HIDDEN ? bg[l*HIDDEN + c] : bx[l*HIDDEN + c - HIDDEN];
    }
}

/* ------------------------------------------------------------------ */
/* Block reduction (256 threads)                                       */
/* ------------------------------------------------------------------ */
__device__ __forceinline__ float2 block_reduce_2(float s, float s2) {
    __shared__ float red[16];
    #pragma unroll
    for (int o = 16; o > 0; o >>= 1) {
        s  += __shfl_down_sync(0xffffffffu, s,  o);
        s2 += __shfl_down_sync(0xffffffffu, s2, o);
    }
    int w = threadIdx.x >> 5, l = threadIdx.x & 31;
    if (l == 0) { red[w] = s; red[8 + w] = s2; }
    __syncthreads();
    if (threadIdx.x < 32) {
        s  = (l < 8) ? red[l]     : 0.f;
        s2 = (l < 8) ? red[8 + l] : 0.f;
        #pragma unroll
        for (int o = 4; o > 0; o >>= 1) {
            s  += __shfl_down_sync(0xffffffffu, s,  o);
            s2 += __shfl_down_sync(0xffffffffu, s2, o);
        }
        if (l == 0) { red[0] = s; red[1] = s2; }
    }
    __syncthreads();
    return make_float2(red[0], red[1]);
}

__device__ __forceinline__ uint32_t pack_h2(float a, float b) {
    __half2 h = __floats2half2_rn(a, b);
    return *(uint32_t*)&h;
}

/* ------------------------------------------------------------------ */
/* LayerNorm over DIM (vectorized)                                     */
/* ------------------------------------------------------------------ */
__global__ void __launch_bounds__(256) ln_kernel(
    const float* __restrict__ x, const float* __restrict__ w,
    const float* __restrict__ b, __half* __restrict__ ohi,
    __half* __restrict__ olo) {
    int t = blockIdx.x;
    int c4 = threadIdx.x;
    float4 v = make_float4(0.f, 0.f, 0.f, 0.f);
    if (c4 < DIM/4) v = ((const float4*)(x + (size_t)t * DIM))[c4];
    float s  = v.x + v.y + v.z + v.w;
    float s2 = v.x*v.x + v.y*v.y + v.z*v.z + v.w*v.w;
    float2 r = block_reduce_2(s, s2);
    float mean = r.x / DIM;
    float var  = r.y / DIM - mean * mean;
    float inv  = rsqrtf(var + EPSF);
    if (c4 < DIM/4) {
        float4 wv = ((const float4*)w)[c4];
        float4 bv = ((const float4*)b)[c4];
        float y0 = (v.x - mean) * inv * wv.x + bv.x;
        float y1 = (v.y - mean) * inv * wv.y + bv.y;
        float y2 = (v.z - mean) * inv * wv.z + bv.z;
        float y3 = (v.w - mean) * inv * wv.w + bv.w;
        __half h0 = __float2half_rn(y0), h1 = __float2half_rn(y1);
        __half h2 = __float2half_rn(y2), h3 = __float2half_rn(y3);
        uint2 hi = make_uint2(pack_h2(y0, y1), pack_h2(y2, y3));
        uint2 lo = make_uint2(pack_h2(y0 - __half2float(h0), y1 - __half2float(h1)),
                              pack_h2(y2 - __half2float(h2), y3 - __half2float(h3)));
        ((uint2*)ohi)[(size_t)t * (DIM/4) + c4] = hi;
        ((uint2*)olo)[(size_t)t * (DIM/4) + c4] = lo;
    }
}

/* ------------------------------------------------------------------ */
/* silu(g)*u then LN over HIDDEN (register-resident)                   */
/* ------------------------------------------------------------------ */
__global__ void __launch_bounds__(256) mlp_act_ln_kernel(
    const float* __restrict__ gu,
    const float* __restrict__ w, const float* __restrict__ b,
    __half* __restrict__ ohi, __half* __restrict__ olo) {
    int t = blockIdx.x;
    const float* gr = gu + (size_t)t * GUS;
    const float* ur = gr + HIDDEN;
    float a[8];
    float s = 0.f, s2 = 0.f;
    #pragma unroll
    for (int j = 0; j < 2; j++) {
        int c4 = threadIdx.x + j * 256;
        float4 gv = ((const float4*)gr)[c4];
        float4 uv = ((const float4*)ur)[c4];
        float* aj = a + j * 4;
        aj[0] = gv.x / (1.f + __expf(-gv.x)) * uv.x;
        aj[1] = gv.y / (1.f + __expf(-gv.y)) * uv.y;
        aj[2] = gv.z / (1.f + __expf(-gv.z)) * uv.z;
        aj[3] = gv.w / (1.f + __expf(-gv.w)) * uv.w;
        s  += aj[0] + aj[1] + aj[2] + aj[3];
        s2 += aj[0]*aj[0] + aj[1]*aj[1] + aj[2]*aj[2] + aj[3]*aj[3];
    }
    float2 r = block_reduce_2(s, s2);
    float mean = r.x / HIDDEN;
    float var  = r.y / HIDDEN - mean * mean;
    float inv  = rsqrtf(var + EPSF);
    #pragma unroll
    for (int j = 0; j < 2; j++) {
        int c4 = threadIdx.x + j * 256;
        float4 wv = ((const float4*)w)[c4];
        float4 bv = ((const float4*)b)[c4];
        float* aj = a + j * 4;
        float y0 = (aj[0] - mean) * inv * wv.x + bv.x;
        float y1 = (aj[1] - mean) * inv * wv.y + bv.y;
        float y2 = (aj[2] - mean) * inv * wv.z + bv.z;
        float y3 = (aj[3] - mean) * inv * wv.w + bv.w;
        __half h0 = __float2half_rn(y0), h1 = __float2half_rn(y1);
        __half h2 = __float2half_rn(y2), h3 = __float2half_rn(y3);
        uint2 hi = make_uint2(pack_h2(y0, y1), pack_h2(y2, y3));
        uint2 lo = make_uint2(pack_h2(y0 - __half2float(h0), y1 - __half2float(h1)),
                              pack_h2(y2 - __half2float(h2), y3 - __half2float(h3)));
        ((uint2*)ohi)[(size_t)t * (HIDDEN/4) + c4] = hi;
        ((uint2*)olo)[(size_t)t * (HIDDEN/4) + c4] = lo;
    }
}

/* ------------------------------------------------------------------ */
/* Attention                                                           */
/* ------------------------------------------------------------------ */
#define KVT 128
__global__ void __launch_bounds__(256) attn_kernel(
    const float* __restrict__ qkv, __half* __restrict__ ohi,
    __half* __restrict__ olo) {
    extern __shared__ float sm[];
    float* Ks = sm;
    float* Vs = sm + KVT * HD;
    int blk = blockIdx.x;
    int half_blk = blk & 1;
    int bh = blk >> 1;
    int b  = bh / HEADS, h = bh % HEADS;
    size_t base_q = (size_t)(b * NTOK) * QS + h * HD;
    int tid = threadIdx.x, lane = tid & 31, wid = tid >> 5;
    int row_local = wid * 16 + (lane & 15);
    int part = lane >> 4;
    int i = half_blk * 128 + row_local;

    const float scale = 0.125f;
    float qreg[32];
    {
        const float* qp = qkv + base_q + (size_t)i * QS + part * 32;
        #pragma unroll
        for (int d = 0; d < 32; d++) qreg[d] = qp[d] * scale;
    }

    float mrun = -1e30f, lrun = 0.f;
    float accv[32];
    #pragma unroll
    for (int d = 0; d < 32; d++) accv[d] = 0.f;

    for (int tkv = 0; tkv < NTOK / KVT; tkv++) {
        for (int idx = tid; idx < KVT * HD; idx += 256) {
            int row = idx >> 6, col = idx & 63;
            size_t src = base_q + (size_t)(tkv * KVT + row) * QS + col;
            Ks[idx] = qkv[src + DIM];
            Vs[idx] = qkv[src + 2*DIM];
        }
        __syncthreads();

        for (int j = 0; j < KVT; j++) {
            const float* kr = Ks + j * HD + part * 32;
            float s = 0.f;
            #pragma unroll
            for (int d = 0; d < 32; d++) s += qreg[d] * kr[d];
            s += __shfl_xor_sync(0xffffffffu, s, 16);
            float mnew = fmaxf(mrun, s);
            float cc = __expf(mrun - mnew);
            float p  = __expf(s - mnew);
            lrun = lrun * cc + p;
            const float* vr = Vs + j * HD + part * 32;
            #pragma unroll
            for (int d = 0; d < 32; d++) accv[d] = accv[d] * cc + p * vr[d];
            mrun = mnew;
        }
        __syncthreads();
    }

    float inv = 1.f / lrun;
    size_t ob = (size_t)(b * NTOK + i) * DIM + h * HD + part * 32;
    #pragma unroll
    for (int d = 0; d < 32; d++) {
        float v0 = accv[d] * inv;
        __half hh = __float2half_rn(v0);
        ohi[ob + d] = hh;
        olo[ob + d] = __float2half_rn(v0 - __half2float(hh));
    }
}

/* ------------------------------------------------------------------ */
/* Launch                                                              */
/* ------------------------------------------------------------------ */
extern "C" void kernel_launch(void* const* d_in, const int* in_sizes, int n_in,
                              void* d_out, int out_size) {
    const float* x      = (const float*)d_in[0];
    const float* pos    = (const float*)d_in[1];
    const float* rope   = (const float*)d_in[2];
    const float* ln1_w  = (const float*)d_in[3];
    const float* ln1_b  = (const float*)d_in[4];
    const float* wq     = (const float*)d_in[5];
    const float* bq     = (const float*)d_in[6];
    const float* wk     = (const float*)d_in[7];
    const float* wv     = (const float*)d_in[8];
    const float* bv     = (const float*)d_in[9];
    const float* wo     = (const float*)d_in[10];
    const float* bo     = (const float*)d_in[11];
    const float* ln2_w  = (const float*)d_in[12];
    const float* ln2_b  = (const float*)d_in[13];
    const float* w1g    = (const float*)d_in[14];
    const float* b1g    = (const float*)d_in[15];
    const float* w1x    = (const float*)d_in[16];
    const float* b1x    = (const float*)d_in[17];
    const float* lnm_w  = (const float*)d_in[18];
    const float* lnm_b  = (const float*)d_in[19];
    const float* w2     = (const float*)d_in[20];
    const float* b2     = (const float*)d_in[21];
    float* h = (float*)d_out;

    float *qkv, *gu, *bqkv, *b1, *part;
    __half *yhh, *yhl, *ohh, *ohl, *mhh, *mhl;
    __half *wqkvh, *wqkvl, *woh, *wol, *w1h, *w1l, *w2h, *w2l;
    cudaGetSymbolAddress((void**)&qkv,   g_qkv);
    cudaGetSymbolAddress((void**)&gu,    g_gu);
    cudaGetSymbolAddress((void**)&part,  g_part);
    cudaGetSymbolAddress((void**)&bqkv,  g_bqkv);
    cudaGetSymbolAddress((void**)&b1,    g_b1);
    cudaGetSymbolAddress((void**)&yhh,   g_yh_hi);
    cudaGetSymbolAddress((void**)&yhl,   g_yh_lo);
    cudaGetSymbolAddress((void**)&ohh,   g_oh_hi);
    cudaGetSymbolAddress((void**)&ohl,   g_oh_lo);
    cudaGetSymbolAddress((void**)&mhh,   g_mh_hi);
    cudaGetSymbolAddress((void**)&mhl,   g_mh_lo);
    cudaGetSymbolAddress((void**)&wqkvh, g_wqkv_hi);
    cudaGetSymbolAddress((void**)&wqkvl, g_wqkv_lo);
    cudaGetSymbolAddress((void**)&woh,   g_wo_hi);
    cudaGetSymbolAddress((void**)&wol,   g_wo_lo);
    cudaGetSymbolAddress((void**)&w1h,   g_w1_hi);
    cudaGetSymbolAddress((void**)&w1l,   g_w1_lo);
    cudaGetSymbolAddress((void**)&w2h,   g_w2_hi);
    cudaGetSymbolAddress((void**)&w2l,   g_w2_lo);

    cudaFuncSetAttribute((const void*)gemm_mma<true,false>,
                         cudaFuncAttributeMaxDynamicSharedMemorySize, GEMM_SMEM);
    cudaFuncSetAttribute((const void*)gemm_mma<false,false>,
                         cudaFuncAttributeMaxDynamicSharedMemorySize, GEMM_SMEM);
    cudaFuncSetAttribute((const void*)gemm_mma<false,true>,
                         cudaFuncAttributeMaxDynamicSharedMemorySize, GEMM_SMEM);
    cudaFuncSetAttribute((const void*)attn_kernel,
                         cudaFuncAttributeMaxDynamicSharedMemorySize,
                         2 * KVT * HD * (int)sizeof(float));

    /* ---- [1] fused weight split + pack ---- */
    {
        const int nD = DIM*DIM, nH = HIDDEN*DIM;
        CvtArgs a;
        const float* srcs[7] = { wq, wk, wv, wo, w1g, w1x, w2 };
        __half* his[7] = { wqkvh, wqkvh, wqkvh, woh, w1h, w1h, w2h };
        __half* los[7] = { wqkvl, wqkvl, wqkvl, wol, w1l, w1l, w2l };
        int lrs[7]   = { nD, nD, nD, nD, nH, nH, nH };
        int ltots[7] = { QS*DIM, QS*DIM, QS*DIM, nD, GUS*DIM, GUS*DIM, nH };
        int offs[7]  = { 0, nD, 2*nD, 0, 0, nH, 0 };
        int cum = 0;
        for (int s = 0; s < 7; s++) {
            a.src[s] = srcs[s]; a.hi[s] = his[s]; a.lo[s] = los[s];
            a.lr[s] = lrs[s]; a.ltot[s] = ltots[s]; a.off[s] = offs[s];
            a.cum[s] = cum;
            cum += DEPTH * lrs[s] / 4;
        }
        a.cum[7] = cum;
        cvt_all<<<(cum + 255)/256, 256>>>(a, cum);
    }
    /* ---- [2] pos-embed add + bias packing ---- */
    add_pos_prep<<<(TOKENS*DIM + 255)/256, 256>>>(x, pos, h, bq, bv, bqkv,
                                                  b1g, b1x, b1);

    dim3 gQKV(QS/256,  TOKENS/128);      /* (9, 32)    */
    dim3 gMLP(GUS/256, TOKENS/128);      /* (16, 32)   */
    dim3 gSK (DIM/256, TOKENS/128, 3);   /* (3, 32, 3) */
    const int RED = (TOKENS*DIM/4 + 255)/256;

    for (int l = 0; l < DEPTH; l++) {
        size_t oqkv = (size_t)l * QS * DIM;
        size_t owo  = (size_t)l * DIM * DIM;
        size_t ow1  = (size_t)l * GUS * DIM;
        size_t ow2  = (size_t)l * DIM * HIDDEN;

        /* ---- attention ---- */
        ln_kernel<<<TOKENS, 256>>>(h, ln1_w + l*DIM, ln1_b + l*DIM, yhh, yhl);
        gemm_mma<true,false><<<gQKV, 256, GEMM_SMEM>>>(
            yhh, yhl, wqkvh + oqkv, wqkvl + oqkv,
            bqkv + l*QS, nullptr, qkv, rope, TOKENS, QS, DIM);
        attn_kernel<<<BATCH*HEADS*2, 256, 2*KVT*HD*sizeof(float)>>>(qkv, ohh, ohl);
        gemm_mma<false,true><<<gSK, 256, GEMM_SMEM>>>(
            ohh, ohl, woh + owo, wol + owo,
            nullptr, nullptr, part, nullptr, TOKENS, DIM, DIM);
        reduce3<<<RED, 256>>>(h, part, bo + l*DIM);

        /* ---- SwiGLU MLP ---- */
        ln_kernel<<<TOKENS, 256>>>(h, ln2_w + l*DIM, ln2_b + l*DIM, yhh, yhl);
        gemm_mma<false,false><<<gMLP, 256, GEMM_SMEM>>>(
            yhh, yhl, w1h + ow1, w1l + ow1,
            b1 + l*GUS, nullptr, gu, nullptr, TOKENS, GUS, DIM);
        mlp_act_ln_kernel<<<TOKENS, 256>>>(gu, lnm_w + l*HIDDEN, lnm_b + l*HIDDEN, mhh, mhl);
        gemm_mma<false,true><<<gSK, 256, GEMM_SMEM>>>(
            mhh, mhl, w2h + ow2, w2l + ow2,
            nullptr, nullptr, part, nullptr, TOKENS, DIM, HIDDEN);
        reduce3<<<RED, 256>>>(h, part, b2 + l*DIM);
    }
}